// round 1
// baseline (speedup 1.0000x reference)
#include <cuda_runtime.h>
#include <cuda_bf16.h>
#include <math.h>

// Problem constants
#define NROWS 16384
#define DIN   1024
#define DEMB  256
#define KCB   1024
#define ALPHA 0.01f
#define EPSV  1e-5f

// Output layout (float32, tuple order concatenated)
#define OFF_X        ((size_t)0)
#define OFF_CODES    ((size_t)16777216)
#define OFF_EMB      ((size_t)16793600)
#define OFF_COMMIT   ((size_t)16793601)
#define OFF_ENT      ((size_t)16793602)
#define OFF_EMA_VECS ((size_t)16793603)
#define OFF_EMA_SIZE ((size_t)17055747)
#define OFF_WEIGHT   ((size_t)17056771)

// Scratch (device globals; no allocations allowed)
__device__ float g_z[NROWS * DEMB];       // 16 MB
__device__ float g_sqr[KCB];
__device__ int   g_codes[NROWS];
__device__ float g_dmin[NROWS];
__device__ float g_upd[KCB * DEMB];       // 1 MB  (segment sums)
__device__ float g_cnt[KCB];
__device__ float g_loss;
__device__ float g_size[KCB];
__device__ float g_Y[KCB * DIN];          // 4 MB  (codebook @ W_recv + b_recv)

// ---------------------------------------------------------------------------
// init: zero accumulators
// grid 1024 x 256 covers 262144
__global__ void k_init() {
    int i = blockIdx.x * blockDim.x + threadIdx.x;
    if (i < KCB * DEMB) g_upd[i] = 0.0f;
    if (i < KCB)        g_cnt[i] = 0.0f;
    if (i == 0)         g_loss  = 0.0f;
}

// ---------------------------------------------------------------------------
// sqr[k] = ||codebook_k||^2 ; grid KCB x 256
__global__ void k_sqr(const float* __restrict__ cb) {
    int k = blockIdx.x, j = threadIdx.x;
    float v = cb[k * DEMB + j];
    float s = v * v;
    #pragma unroll
    for (int o = 16; o > 0; o >>= 1) s += __shfl_xor_sync(0xffffffffu, s, o);
    __shared__ float wsum[8];
    if ((j & 31) == 0) wsum[j >> 5] = s;
    __syncthreads();
    if (j == 0) {
        float tot = 0.0f;
        #pragma unroll
        for (int w = 0; w < 8; w++) tot += wsum[w];
        g_sqr[k] = tot;
    }
}

// ---------------------------------------------------------------------------
// Generic fp32 SGEMM: C[M,Nc] = A[M,Kd] @ B[Kd,Nc] + bias[Nc]
// BM=128 BN=128 BK=16, 256 threads, 8x8 per-thread microtile.
// Requires M%128==0, Nc%128==0, Kd%16==0.
__global__ __launch_bounds__(256) void k_sgemm(
    const float* __restrict__ A, const float* __restrict__ B,
    const float* __restrict__ bias, float* __restrict__ C,
    int M, int Nc, int Kd)
{
    __shared__ float As[16][128];   // transposed: As[k][m]
    __shared__ float Bs[16][128];   // Bs[k][n]
    const int tid = threadIdx.x;
    const int bx = blockIdx.x;      // N tile
    const int by = blockIdx.y;      // M tile
    const int tr = tid >> 4;        // 0..15
    const int tc = tid & 15;        // 0..15

    const int aRow = tid >> 2;          // 0..63 (two passes +64)
    const int aCol = (tid & 3) * 4;     // 0,4,8,12
    const int bRow = tid >> 5;          // 0..7  (two passes +8)
    const int bCol = (tid & 31) * 4;    // 0..124

    const float* Ab = A + (size_t)(by * 128) * Kd;
    const float* Bb = B + bx * 128;

    float acc[8][8];
    #pragma unroll
    for (int i = 0; i < 8; i++)
        #pragma unroll
        for (int j = 0; j < 8; j++) acc[i][j] = 0.0f;

    for (int k0 = 0; k0 < Kd; k0 += 16) {
        #pragma unroll
        for (int p = 0; p < 2; p++) {
            int m = aRow + p * 64;
            float4 v = *reinterpret_cast<const float4*>(Ab + (size_t)m * Kd + k0 + aCol);
            As[aCol + 0][m] = v.x; As[aCol + 1][m] = v.y;
            As[aCol + 2][m] = v.z; As[aCol + 3][m] = v.w;
        }
        #pragma unroll
        for (int p = 0; p < 2; p++) {
            int r = bRow + p * 8;
            float4 v = *reinterpret_cast<const float4*>(Bb + (size_t)(k0 + r) * Nc + bCol);
            *reinterpret_cast<float4*>(&Bs[r][bCol]) = v;
        }
        __syncthreads();
        #pragma unroll
        for (int kk = 0; kk < 16; kk++) {
            float4 a0 = *reinterpret_cast<const float4*>(&As[kk][tr * 8]);
            float4 a1 = *reinterpret_cast<const float4*>(&As[kk][tr * 8 + 4]);
            float4 b0 = *reinterpret_cast<const float4*>(&Bs[kk][tc * 8]);
            float4 b1 = *reinterpret_cast<const float4*>(&Bs[kk][tc * 8 + 4]);
            float av[8] = {a0.x, a0.y, a0.z, a0.w, a1.x, a1.y, a1.z, a1.w};
            float bv[8] = {b0.x, b0.y, b0.z, b0.w, b1.x, b1.y, b1.z, b1.w};
            #pragma unroll
            for (int i = 0; i < 8; i++)
                #pragma unroll
                for (int j = 0; j < 8; j++) acc[i][j] += av[i] * bv[j];
        }
        __syncthreads();
    }

    int row0 = by * 128 + tr * 8;
    int col0 = bx * 128 + tc * 8;
    float4 bb0 = *reinterpret_cast<const float4*>(bias + col0);
    float4 bb1 = *reinterpret_cast<const float4*>(bias + col0 + 4);
    float bvec[8] = {bb0.x, bb0.y, bb0.z, bb0.w, bb1.x, bb1.y, bb1.z, bb1.w};
    #pragma unroll
    for (int i = 0; i < 8; i++) {
        float4 o0 = make_float4(acc[i][0] + bvec[0], acc[i][1] + bvec[1],
                                acc[i][2] + bvec[2], acc[i][3] + bvec[3]);
        float4 o1 = make_float4(acc[i][4] + bvec[4], acc[i][5] + bvec[5],
                                acc[i][6] + bvec[6], acc[i][7] + bvec[7]);
        *reinterpret_cast<float4*>(C + (size_t)(row0 + i) * Nc + col0)     = o0;
        *reinterpret_cast<float4*>(C + (size_t)(row0 + i) * Nc + col0 + 4) = o1;
    }
}

// ---------------------------------------------------------------------------
// Fused distance-GEMM + argmin: for each row n of z, codes[n] = argmin_k
// (sqr[k] - 2 * <z_n, cb_k>). 64 rows/block, chunks of 128 codes, BK=32.
// grid 256 x 256.
__global__ __launch_bounds__(256) void k_argmin(
    const float* __restrict__ cb, float* __restrict__ out)
{
    __shared__ float Zs[32][64];    // 8 KB, transposed z tile
    __shared__ float Cs[32][128];   // 16 KB, transposed codebook tile
    __shared__ float redv[4][16][16];
    __shared__ int   redk[4][16][16];

    const int tid = threadIdx.x;
    const int by  = blockIdx.x;     // 64 rows per block
    const int tr  = tid >> 4;       // 0..15 -> rows tr*4..tr*4+3
    const int tc  = tid & 15;       // 0..15 -> code lanes tc*8..tc*8+7
    const int lm  = tid >> 3;       // 0..31 load index
    const int lk  = (tid & 7) * 4;  // 0..28

    float best[4]  = {3.4e38f, 3.4e38f, 3.4e38f, 3.4e38f};
    int   bestk[4] = {0, 0, 0, 0};

    for (int c = 0; c < 8; c++) {           // 8 chunks of 128 codes
        float acc[4][8];
        #pragma unroll
        for (int i = 0; i < 4; i++)
            #pragma unroll
            for (int j = 0; j < 8; j++) acc[i][j] = 0.0f;

        for (int kb = 0; kb < 8; kb++) {    // 256 / 32
            #pragma unroll
            for (int p = 0; p < 2; p++) {
                int m = lm + p * 32;
                float4 v = *reinterpret_cast<const float4*>(
                    g_z + (size_t)(by * 64 + m) * DEMB + kb * 32 + lk);
                Zs[lk + 0][m] = v.x; Zs[lk + 1][m] = v.y;
                Zs[lk + 2][m] = v.z; Zs[lk + 3][m] = v.w;
            }
            #pragma unroll
            for (int p = 0; p < 4; p++) {
                int n = lm + p * 32;
                float4 v = *reinterpret_cast<const float4*>(
                    cb + (size_t)(c * 128 + n) * DEMB + kb * 32 + lk);
                Cs[lk + 0][n] = v.x; Cs[lk + 1][n] = v.y;
                Cs[lk + 2][n] = v.z; Cs[lk + 3][n] = v.w;
            }
            __syncthreads();
            #pragma unroll
            for (int kk = 0; kk < 32; kk++) {
                float4 a  = *reinterpret_cast<const float4*>(&Zs[kk][tr * 4]);
                float4 b0 = *reinterpret_cast<const float4*>(&Cs[kk][tc * 8]);
                float4 b1 = *reinterpret_cast<const float4*>(&Cs[kk][tc * 8 + 4]);
                float av[4] = {a.x, a.y, a.z, a.w};
                float bv[8] = {b0.x, b0.y, b0.z, b0.w, b1.x, b1.y, b1.z, b1.w};
                #pragma unroll
                for (int i = 0; i < 4; i++)
                    #pragma unroll
                    for (int j = 0; j < 8; j++) acc[i][j] += av[i] * bv[j];
            }
            __syncthreads();
        }
        // fold this chunk of codes into running argmin (code order ascending)
        #pragma unroll
        for (int j = 0; j < 8; j++) {
            int k = c * 128 + tc * 8 + j;
            float s = g_sqr[k];
            #pragma unroll
            for (int i = 0; i < 4; i++) {
                float d = s - 2.0f * acc[i][j];
                if (d < best[i]) { best[i] = d; bestk[i] = k; }
            }
        }
    }

    #pragma unroll
    for (int i = 0; i < 4; i++) {
        redv[i][tr][tc] = best[i];
        redk[i][tr][tc] = bestk[i];
    }
    __syncthreads();
    if (tid < 64) {
        int i = tid & 3, r = tid >> 2;
        float bv = redv[i][r][0];
        int   bk = redk[i][r][0];
        #pragma unroll
        for (int t2 = 1; t2 < 16; t2++) {       // ascending code order
            float v = redv[i][r][t2];
            if (v < bv) { bv = v; bk = redk[i][r][t2]; }
        }
        int row = by * 64 + r * 4 + i;
        g_codes[row] = bk;
        g_dmin[row]  = bv;
        out[OFF_CODES + row] = (float)bk;
    }
}

// ---------------------------------------------------------------------------
// Scatter: segment-sum z into g_upd by code, counts, and loss accumulation.
// loss_n = ||z_n||^2 + dmin_n  (== ||z_n - cb[code]||^2). grid NROWS x 256.
__global__ __launch_bounds__(256) void k_scatter() {
    int row  = blockIdx.x;
    int code = g_codes[row];
    int j    = threadIdx.x;
    float v  = g_z[(size_t)row * DEMB + j];
    atomicAdd(&g_upd[(size_t)code * DEMB + j], v);
    float sq = v * v;
    #pragma unroll
    for (int o = 16; o > 0; o >>= 1) sq += __shfl_xor_sync(0xffffffffu, sq, o);
    __shared__ float wsum[8];
    if ((j & 31) == 0) wsum[j >> 5] = sq;
    __syncthreads();
    if (j == 0) {
        float tot = 0.0f;
        #pragma unroll
        for (int w = 0; w < 8; w++) tot += wsum[w];
        atomicAdd(&g_loss, tot + g_dmin[row]);
        atomicAdd(&g_cnt[code], 1.0f);
    }
}

// ---------------------------------------------------------------------------
// Finalize scalars + ema_size + size[] ; single block of 1024 threads.
__global__ __launch_bounds__(1024) void k_final_small(
    const float* __restrict__ ema_size_in, float* __restrict__ out)
{
    __shared__ float sh[1024];
    int t = threadIdx.x;
    float cnt = g_cnt[t];
    float esz = ema_size_in[t] + ALPHA * (cnt - ema_size_in[t]);
    out[OFF_EMA_SIZE + t] = esz;

    sh[t] = esz;
    __syncthreads();
    for (int s = 512; s > 0; s >>= 1) {
        if (t < s) sh[t] += sh[t + s];
        __syncthreads();
    }
    float n = sh[0];
    __syncthreads();

    float coef = n / (n + (float)KCB * EPSV);
    g_size[t]  = coef * (esz + EPSV);

    float p = cnt * (1.0f / (float)NROWS);
    float e = (cnt > 0.0f) ? (-p * logf(p)) : 0.0f;
    sh[t] = e;
    __syncthreads();
    for (int s = 512; s > 0; s >>= 1) {
        if (t < s) sh[t] += sh[t + s];
        __syncthreads();
    }
    if (t == 0) {
        out[OFF_ENT]    = sh[0] / logf(2.0f);
        out[OFF_EMB]    = g_loss;
        out[OFF_COMMIT] = g_loss;
    }
}

// ---------------------------------------------------------------------------
// ema_vecs_new + weight_new ; grid 1024 x 256 -> 262144 elems.
__global__ void k_ema(const float* __restrict__ ema_vecs_in, float* __restrict__ out) {
    int i = blockIdx.x * blockDim.x + threadIdx.x;
    float v = ema_vecs_in[i] + ALPHA * (g_upd[i] - ema_vecs_in[i]);
    out[OFF_EMA_VECS + i] = v;
    out[OFF_WEIGHT + i]   = v / g_size[i >> 8];   // row k = i / DEMB
}

// ---------------------------------------------------------------------------
// x[n,:] = Y[codes[n],:]  (Y is L2-resident) ; grid NROWS x 256 (float4).
__global__ __launch_bounds__(256) void k_gather(float* __restrict__ out) {
    int row  = blockIdx.x;
    int code = g_codes[row];
    const float4* src = reinterpret_cast<const float4*>(g_Y + (size_t)code * DIN);
    float4* dst = reinterpret_cast<float4*>(out + OFF_X + (size_t)row * DIN);
    dst[threadIdx.x] = src[threadIdx.x];
}

// ---------------------------------------------------------------------------
extern "C" void kernel_launch(void* const* d_in, const int* in_sizes, int n_in,
                              void* d_out, int out_size) {
    const float* input    = (const float*)d_in[0];
    const float* W_send   = (const float*)d_in[1];
    const float* b_send   = (const float*)d_in[2];
    const float* W_recv   = (const float*)d_in[3];
    const float* b_recv   = (const float*)d_in[4];
    const float* codebook = (const float*)d_in[5];
    const float* ema_vecs = (const float*)d_in[6];
    const float* ema_size = (const float*)d_in[7];
    float* out = (float*)d_out;

    float* z_ptr; cudaGetSymbolAddress((void**)&z_ptr, g_z);
    float* Y_ptr; cudaGetSymbolAddress((void**)&Y_ptr, g_Y);

    k_init<<<1024, 256>>>();
    k_sqr<<<KCB, 256>>>(codebook);
    // z = input @ W_send + b_send : M=16384, Nc=256, Kd=1024
    k_sgemm<<<dim3(2, 128), 256>>>(input, W_send, b_send, z_ptr, NROWS, DEMB, DIN);
    k_argmin<<<256, 256>>>(codebook, out);
    k_scatter<<<NROWS, 256>>>();
    k_final_small<<<1, 1024>>>(ema_size, out);
    k_ema<<<1024, 256>>>(ema_vecs, out);
    // Y = codebook @ W_recv + b_recv : M=1024, Nc=1024, Kd=256
    k_sgemm<<<dim3(8, 8), 256>>>(codebook, W_recv, b_recv, Y_ptr, KCB, DIN, DEMB);
    k_gather<<<NROWS, 256>>>(out);
}

// round 2
// speedup vs baseline: 1.3239x; 1.3239x over previous
#include <cuda_runtime.h>
#include <cuda_bf16.h>
#include <math.h>

// Problem constants
#define NROWS 16384
#define DIN   1024
#define DEMB  256
#define KCB   1024
#define ALPHA 0.01f
#define EPSV  1e-5f

// Output layout (float32, tuple order concatenated)
#define OFF_X        ((size_t)0)
#define OFF_CODES    ((size_t)16777216)
#define OFF_EMB      ((size_t)16793600)
#define OFF_COMMIT   ((size_t)16793601)
#define OFF_ENT      ((size_t)16793602)
#define OFF_EMA_VECS ((size_t)16793603)
#define OFF_EMA_SIZE ((size_t)17055747)
#define OFF_WEIGHT   ((size_t)17056771)

// Scratch (device globals; no allocations allowed)
__device__ float g_z[NROWS * DEMB];       // 16 MB
__device__ float g_sqr[KCB];
__device__ int   g_codes[NROWS];
__device__ float g_dmin[NROWS];
__device__ float g_upd[KCB * DEMB];       // 1 MB  (segment sums)
__device__ float g_cnt[KCB];
__device__ float g_loss;
__device__ float g_size[KCB];
__device__ float g_Y[KCB * DIN];          // 4 MB  (codebook @ W_recv + b_recv)
__device__ unsigned long long g_best[NROWS];  // packed (sortable_dist<<32 | code)

// ---------------------------------------------------------------------------
// init: zero accumulators, set argmin sentinels. grid 1024 x 256 covers 262144
__global__ void k_init() {
    int i = blockIdx.x * blockDim.x + threadIdx.x;
    if (i < KCB * DEMB) g_upd[i] = 0.0f;
    if (i < KCB)        g_cnt[i] = 0.0f;
    if (i < NROWS)      g_best[i] = 0xFFFFFFFFFFFFFFFFull;
    if (i == 0)         g_loss  = 0.0f;
}

// ---------------------------------------------------------------------------
// sqr[k] = ||codebook_k||^2 ; grid KCB x 256
__global__ void k_sqr(const float* __restrict__ cb) {
    int k = blockIdx.x, j = threadIdx.x;
    float v = cb[k * DEMB + j];
    float s = v * v;
    #pragma unroll
    for (int o = 16; o > 0; o >>= 1) s += __shfl_xor_sync(0xffffffffu, s, o);
    __shared__ float wsum[8];
    if ((j & 31) == 0) wsum[j >> 5] = s;
    __syncthreads();
    if (j == 0) {
        float tot = 0.0f;
        #pragma unroll
        for (int w = 0; w < 8; w++) tot += wsum[w];
        g_sqr[k] = tot;
    }
}

// ---------------------------------------------------------------------------
// Generic fp32 SGEMM: C[M,Nc] = A[M,Kd] @ B[Kd,Nc] + bias[Nc]
// BM=128 BN=128 BK=16, 256 threads, 8x8 per-thread microtile.
__global__ __launch_bounds__(256) void k_sgemm(
    const float* __restrict__ A, const float* __restrict__ B,
    const float* __restrict__ bias, float* __restrict__ C,
    int M, int Nc, int Kd)
{
    __shared__ float As[16][128];   // transposed: As[k][m]
    __shared__ float Bs[16][128];   // Bs[k][n]
    const int tid = threadIdx.x;
    const int bx = blockIdx.x;      // N tile
    const int by = blockIdx.y;      // M tile
    const int tr = tid >> 4;        // 0..15
    const int tc = tid & 15;        // 0..15

    const int aRow = tid >> 2;          // 0..63 (two passes +64)
    const int aCol = (tid & 3) * 4;     // 0,4,8,12
    const int bRow = tid >> 5;          // 0..7  (two passes +8)
    const int bCol = (tid & 31) * 4;    // 0..124

    const float* Ab = A + (size_t)(by * 128) * Kd;
    const float* Bb = B + bx * 128;

    float acc[8][8];
    #pragma unroll
    for (int i = 0; i < 8; i++)
        #pragma unroll
        for (int j = 0; j < 8; j++) acc[i][j] = 0.0f;

    for (int k0 = 0; k0 < Kd; k0 += 16) {
        #pragma unroll
        for (int p = 0; p < 2; p++) {
            int m = aRow + p * 64;
            float4 v = *reinterpret_cast<const float4*>(Ab + (size_t)m * Kd + k0 + aCol);
            As[aCol + 0][m] = v.x; As[aCol + 1][m] = v.y;
            As[aCol + 2][m] = v.z; As[aCol + 3][m] = v.w;
        }
        #pragma unroll
        for (int p = 0; p < 2; p++) {
            int r = bRow + p * 8;
            float4 v = *reinterpret_cast<const float4*>(Bb + (size_t)(k0 + r) * Nc + bCol);
            *reinterpret_cast<float4*>(&Bs[r][bCol]) = v;
        }
        __syncthreads();
        #pragma unroll
        for (int kk = 0; kk < 16; kk++) {
            float4 a0 = *reinterpret_cast<const float4*>(&As[kk][tr * 8]);
            float4 a1 = *reinterpret_cast<const float4*>(&As[kk][tr * 8 + 4]);
            float4 b0 = *reinterpret_cast<const float4*>(&Bs[kk][tc * 8]);
            float4 b1 = *reinterpret_cast<const float4*>(&Bs[kk][tc * 8 + 4]);
            float av[8] = {a0.x, a0.y, a0.z, a0.w, a1.x, a1.y, a1.z, a1.w};
            float bv[8] = {b0.x, b0.y, b0.z, b0.w, b1.x, b1.y, b1.z, b1.w};
            #pragma unroll
            for (int i = 0; i < 8; i++)
                #pragma unroll
                for (int j = 0; j < 8; j++) acc[i][j] += av[i] * bv[j];
        }
        __syncthreads();
    }

    int row0 = by * 128 + tr * 8;
    int col0 = bx * 128 + tc * 8;
    float4 bb0 = *reinterpret_cast<const float4*>(bias + col0);
    float4 bb1 = *reinterpret_cast<const float4*>(bias + col0 + 4);
    float bvec[8] = {bb0.x, bb0.y, bb0.z, bb0.w, bb1.x, bb1.y, bb1.z, bb1.w};
    #pragma unroll
    for (int i = 0; i < 8; i++) {
        float4 o0 = make_float4(acc[i][0] + bvec[0], acc[i][1] + bvec[1],
                                acc[i][2] + bvec[2], acc[i][3] + bvec[3]);
        float4 o1 = make_float4(acc[i][4] + bvec[4], acc[i][5] + bvec[5],
                                acc[i][6] + bvec[6], acc[i][7] + bvec[7]);
        *reinterpret_cast<float4*>(C + (size_t)(row0 + i) * Nc + col0)     = o0;
        *reinterpret_cast<float4*>(C + (size_t)(row0 + i) * Nc + col0 + 4) = o1;
    }
}

// ---------------------------------------------------------------------------
// Distance-GEMM + tile-local argmin + cross-tile atomicMin.
// Tile: 128 rows x 128 codes, K=256 full. 8x8 microtile, 256 threads.
// Grid: (8 code tiles, 128 row tiles). Smem row stride 132 -> conflict-free
// transposed stores, still 16B-aligned for float4 reads.
__global__ __launch_bounds__(256) void k_argmin(const float* __restrict__ cb)
{
    __shared__ float Zs[16 * 132];
    __shared__ float Cs[16 * 132];

    const int tid   = threadIdx.x;
    const int code0 = blockIdx.x * 128;
    const int row0  = blockIdx.y * 128;
    const int tr = tid >> 4;          // 0..15 (rows tr*8..)
    const int tc = tid & 15;          // 0..15 (codes tc*8..)
    const int lm = tid >> 2;          // 0..63
    const int lk = (tid & 3) * 4;     // 0,4,8,12

    float acc[8][8];
    #pragma unroll
    for (int i = 0; i < 8; i++)
        #pragma unroll
        for (int j = 0; j < 8; j++) acc[i][j] = 0.0f;

    for (int k0 = 0; k0 < DEMB; k0 += 16) {
        #pragma unroll
        for (int p = 0; p < 2; p++) {
            int m = lm + p * 64;
            float4 v = *reinterpret_cast<const float4*>(
                g_z + (size_t)(row0 + m) * DEMB + k0 + lk);
            Zs[(lk + 0) * 132 + m] = v.x; Zs[(lk + 1) * 132 + m] = v.y;
            Zs[(lk + 2) * 132 + m] = v.z; Zs[(lk + 3) * 132 + m] = v.w;
            float4 w = *reinterpret_cast<const float4*>(
                cb + (size_t)(code0 + m) * DEMB + k0 + lk);
            Cs[(lk + 0) * 132 + m] = w.x; Cs[(lk + 1) * 132 + m] = w.y;
            Cs[(lk + 2) * 132 + m] = w.z; Cs[(lk + 3) * 132 + m] = w.w;
        }
        __syncthreads();
        #pragma unroll
        for (int kk = 0; kk < 16; kk++) {
            float4 a0 = *reinterpret_cast<const float4*>(Zs + kk * 132 + tr * 8);
            float4 a1 = *reinterpret_cast<const float4*>(Zs + kk * 132 + tr * 8 + 4);
            float4 b0 = *reinterpret_cast<const float4*>(Cs + kk * 132 + tc * 8);
            float4 b1 = *reinterpret_cast<const float4*>(Cs + kk * 132 + tc * 8 + 4);
            float av[8] = {a0.x, a0.y, a0.z, a0.w, a1.x, a1.y, a1.z, a1.w};
            float bv[8] = {b0.x, b0.y, b0.z, b0.w, b1.x, b1.y, b1.z, b1.w};
            #pragma unroll
            for (int i = 0; i < 8; i++)
                #pragma unroll
                for (int j = 0; j < 8; j++) acc[i][j] += av[i] * bv[j];
        }
        __syncthreads();
    }

    // epilogue: d = sqr[k] - 2*cov; pack (sortable_dist, code); reduce 16 lanes
    float sq[8];
    #pragma unroll
    for (int j = 0; j < 8; j++) sq[j] = g_sqr[code0 + tc * 8 + j];

    #pragma unroll
    for (int i = 0; i < 8; i++) {
        unsigned long long best = 0xFFFFFFFFFFFFFFFFull;
        #pragma unroll
        for (int j = 0; j < 8; j++) {
            float d = fmaf(-2.0f, acc[i][j], sq[j]);
            unsigned u = __float_as_uint(d);
            u = (u & 0x80000000u) ? ~u : (u | 0x80000000u);   // sortable
            unsigned long long p =
                ((unsigned long long)u << 32) | (unsigned)(code0 + tc * 8 + j);
            if (p < best) best = p;
        }
        // tc-group (16 consecutive lanes, within one warp half)
        #pragma unroll
        for (int off = 8; off > 0; off >>= 1) {
            unsigned long long o = __shfl_xor_sync(0xffffffffu, best, off);
            if (o < best) best = o;
        }
        if (tc == 0) atomicMin(&g_best[row0 + tr * 8 + i], best);
    }
}

// ---------------------------------------------------------------------------
// Decode packed argmin winners. grid 64 x 256.
__global__ void k_codes(float* __restrict__ out) {
    int i = blockIdx.x * blockDim.x + threadIdx.x;
    if (i >= NROWS) return;
    unsigned long long p = g_best[i];
    int k = (int)(unsigned)(p & 0xFFFFFFFFull);
    unsigned ue = (unsigned)(p >> 32);
    float d = (ue & 0x80000000u) ? __uint_as_float(ue & 0x7FFFFFFFu)
                                 : __uint_as_float(~ue);
    g_codes[i] = k;
    g_dmin[i]  = d;
    out[OFF_CODES + i] = (float)k;
}

// ---------------------------------------------------------------------------
// Scatter: segment-sum z into g_upd by code, counts, loss. grid NROWS x 256.
__global__ __launch_bounds__(256) void k_scatter() {
    int row  = blockIdx.x;
    int code = g_codes[row];
    int j    = threadIdx.x;
    float v  = g_z[(size_t)row * DEMB + j];
    atomicAdd(&g_upd[(size_t)code * DEMB + j], v);
    float sq = v * v;
    #pragma unroll
    for (int o = 16; o > 0; o >>= 1) sq += __shfl_xor_sync(0xffffffffu, sq, o);
    __shared__ float wsum[8];
    if ((j & 31) == 0) wsum[j >> 5] = sq;
    __syncthreads();
    if (j == 0) {
        float tot = 0.0f;
        #pragma unroll
        for (int w = 0; w < 8; w++) tot += wsum[w];
        atomicAdd(&g_loss, tot + g_dmin[row]);
        atomicAdd(&g_cnt[code], 1.0f);
    }
}

// ---------------------------------------------------------------------------
// Finalize scalars + ema_size + size[] ; single block of 1024 threads.
__global__ __launch_bounds__(1024) void k_final_small(
    const float* __restrict__ ema_size_in, float* __restrict__ out)
{
    __shared__ float sh[1024];
    int t = threadIdx.x;
    float cnt = g_cnt[t];
    float esz = ema_size_in[t] + ALPHA * (cnt - ema_size_in[t]);
    out[OFF_EMA_SIZE + t] = esz;

    sh[t] = esz;
    __syncthreads();
    for (int s = 512; s > 0; s >>= 1) {
        if (t < s) sh[t] += sh[t + s];
        __syncthreads();
    }
    float n = sh[0];
    __syncthreads();

    float coef = n / (n + (float)KCB * EPSV);
    g_size[t]  = coef * (esz + EPSV);

    float p = cnt * (1.0f / (float)NROWS);
    float e = (cnt > 0.0f) ? (-p * logf(p)) : 0.0f;
    sh[t] = e;
    __syncthreads();
    for (int s = 512; s > 0; s >>= 1) {
        if (t < s) sh[t] += sh[t + s];
        __syncthreads();
    }
    if (t == 0) {
        out[OFF_ENT]    = sh[0] / logf(2.0f);
        out[OFF_EMB]    = g_loss;
        out[OFF_COMMIT] = g_loss;
    }
}

// ---------------------------------------------------------------------------
// ema_vecs_new + weight_new ; grid 1024 x 256 -> 262144 elems.
__global__ void k_ema(const float* __restrict__ ema_vecs_in, float* __restrict__ out) {
    int i = blockIdx.x * blockDim.x + threadIdx.x;
    float v = ema_vecs_in[i] + ALPHA * (g_upd[i] - ema_vecs_in[i]);
    out[OFF_EMA_VECS + i] = v;
    out[OFF_WEIGHT + i]   = v / g_size[i >> 8];   // row k = i / DEMB
}

// ---------------------------------------------------------------------------
// x[n,:] = Y[codes[n],:]  (Y is L2-resident) ; grid NROWS x 256 (float4).
__global__ __launch_bounds__(256) void k_gather(float* __restrict__ out) {
    int row  = blockIdx.x;
    int code = g_codes[row];
    const float4* src = reinterpret_cast<const float4*>(g_Y + (size_t)code * DIN);
    float4* dst = reinterpret_cast<float4*>(out + OFF_X + (size_t)row * DIN);
    dst[threadIdx.x] = src[threadIdx.x];
}

// ---------------------------------------------------------------------------
extern "C" void kernel_launch(void* const* d_in, const int* in_sizes, int n_in,
                              void* d_out, int out_size) {
    const float* input    = (const float*)d_in[0];
    const float* W_send   = (const float*)d_in[1];
    const float* b_send   = (const float*)d_in[2];
    const float* W_recv   = (const float*)d_in[3];
    const float* b_recv   = (const float*)d_in[4];
    const float* codebook = (const float*)d_in[5];
    const float* ema_vecs = (const float*)d_in[6];
    const float* ema_size = (const float*)d_in[7];
    float* out = (float*)d_out;

    float* z_ptr; cudaGetSymbolAddress((void**)&z_ptr, g_z);
    float* Y_ptr; cudaGetSymbolAddress((void**)&Y_ptr, g_Y);

    k_init<<<1024, 256>>>();
    k_sqr<<<KCB, 256>>>(codebook);
    // z = input @ W_send + b_send : M=16384, Nc=256, Kd=1024
    k_sgemm<<<dim3(2, 128), 256>>>(input, W_send, b_send, z_ptr, NROWS, DEMB, DIN);
    // Y = codebook @ W_recv + b_recv : M=1024, Nc=1024, Kd=256 (independent of z)
    k_sgemm<<<dim3(8, 8), 256>>>(codebook, W_recv, b_recv, Y_ptr, KCB, DIN, DEMB);
    // argmin over 128x128 tiles, grid (codeTiles=8, rowTiles=128)
    k_argmin<<<dim3(8, 128), 256>>>(codebook);
    k_codes<<<64, 256>>>(out);
    k_scatter<<<NROWS, 256>>>();
    k_final_small<<<1, 1024>>>(ema_size, out);
    k_ema<<<1024, 256>>>(ema_vecs, out);
    k_gather<<<NROWS, 256>>>(out);
}

// round 5
// speedup vs baseline: 1.4601x; 1.1029x over previous
#include <cuda_runtime.h>
#include <cuda_bf16.h>
#include <math.h>
#include <stdint.h>

// Problem constants
#define NROWS 16384
#define DIN   1024
#define DEMB  256
#define KCB   1024
#define ALPHA 0.01f
#define EPSV  1e-5f

// Output layout (float32, tuple order concatenated)
#define OFF_X        ((size_t)0)
#define OFF_CODES    ((size_t)16777216)
#define OFF_EMB      ((size_t)16793600)
#define OFF_COMMIT   ((size_t)16793601)
#define OFF_ENT      ((size_t)16793602)
#define OFF_EMA_VECS ((size_t)16793603)
#define OFF_EMA_SIZE ((size_t)17055747)
#define OFF_WEIGHT   ((size_t)17056771)

// ---------------------------------------------------------------------------
// Scratch (device globals; no allocations allowed)
__device__ float g_z[NROWS * DEMB];       // fp32 z
__device__ float g_sqr[KCB];
__device__ int   g_codes[NROWS];
__device__ float g_dmin[NROWS];
__device__ float g_upd[KCB * DEMB];
__device__ float g_cnt[KCB];
__device__ float g_loss;
__device__ float g_size[KCB];
__device__ float g_Y[KCB * DIN];          // codebook @ W_recv + b_recv
__device__ unsigned long long g_best[NROWS];
__device__ float g_wsT[DEMB * DIN];       // W_send^T [256,1024]
__device__ float g_wrT[DIN * DEMB];       // W_recv^T [1024,256]

// ---------------------------------------------------------------------------
__device__ __forceinline__ uint32_t smem_u32(const void* p) {
    uint32_t a;
    asm("{ .reg .u64 t; cvta.to.shared.u64 t, %1; cvt.u32.u64 %0, t; }" : "=r"(a) : "l"(p));
    return a;
}
__device__ __forceinline__ void ldsm4(uint32_t* r, uint32_t addr) {
    asm volatile("ldmatrix.sync.aligned.m8n8.x4.shared.b16 {%0,%1,%2,%3}, [%4];"
                 : "=r"(r[0]), "=r"(r[1]), "=r"(r[2]), "=r"(r[3]) : "r"(addr));
}
__device__ __forceinline__ void mma_tf32(float* c, const uint32_t* a, const uint32_t* b) {
    asm volatile("mma.sync.aligned.m16n8k8.row.col.f32.tf32.tf32.f32 "
                 "{%0,%1,%2,%3}, {%4,%5,%6,%7}, {%8,%9}, {%0,%1,%2,%3};"
                 : "+f"(c[0]), "+f"(c[1]), "+f"(c[2]), "+f"(c[3])
                 : "r"(a[0]), "r"(a[1]), "r"(a[2]), "r"(a[3]), "r"(b[0]), "r"(b[1]));
}
__device__ __forceinline__ uint32_t f2tf32(float x) {
    uint32_t r;
    asm("cvt.rna.tf32.f32 %0, %1;" : "=r"(r) : "f"(x));
    return r;
}
__device__ __forceinline__ void split_tf32(uint32_t raw, uint32_t& hi, uint32_t& lo) {
    float x = __uint_as_float(raw);
    hi = f2tf32(x);
    lo = f2tf32(x - __uint_as_float(hi));
}

#define STRIDE 36   // fp32 units per smem row (144 B): conflict-free ldmatrix

// ---------------------------------------------------------------------------
// Split-TF32 3-product GEMM core (3xTF32): acc += A @ B^T in ~fp32 accuracy.
// CTA tile 128(M) x 128(N), K chunks of 32 fp32. 8 warps 2x4, warp 64x32,
// m16n8k8 tiles. A row-major [*, kdim]; B row-major [N, kdim].
__device__ __forceinline__ void gemm_core32(
    const float* __restrict__ A, const float* __restrict__ B,
    int row0, int col0, int kdim,
    float* sA, float* sB, float acc[4][4][4])
{
    const int tid  = threadIdx.x;
    const int lane = tid & 31;
    const int wid  = tid >> 5;
    const int warp_m = wid >> 2;     // 0..1
    const int warp_n = wid & 3;      // 0..3

    const uint32_t aA = smem_u32(sA), aB = smem_u32(sB);

    const int r      = tid >> 1;          // 0..127 load row
    const int cshift = (tid & 1) * 16;    // 0 or 16 (fp32)

    // ldmatrix lane address components (fp32-unit row/col, b16-viewed)
    const int frow = lane & 15;           // row within 16-row group
    const int fcol = (lane >> 4) * 4;     // fp32 col half: 0 or 4

    for (int kc = 0; kc < kdim; kc += 32) {
        __syncthreads();
        {
            size_t ga = (size_t)(row0 + r) * kdim + kc + cshift;
            size_t gb = (size_t)(col0 + r) * kdim + kc + cshift;
            float4 va0 = *reinterpret_cast<const float4*>(A + ga);
            float4 va1 = *reinterpret_cast<const float4*>(A + ga + 4);
            float4 va2 = *reinterpret_cast<const float4*>(A + ga + 8);
            float4 va3 = *reinterpret_cast<const float4*>(A + ga + 12);
            float4 vb0 = *reinterpret_cast<const float4*>(B + gb);
            float4 vb1 = *reinterpret_cast<const float4*>(B + gb + 4);
            float4 vb2 = *reinterpret_cast<const float4*>(B + gb + 8);
            float4 vb3 = *reinterpret_cast<const float4*>(B + gb + 12);
            int so = r * STRIDE + cshift;
            *reinterpret_cast<float4*>(sA + so)      = va0;
            *reinterpret_cast<float4*>(sA + so + 4)  = va1;
            *reinterpret_cast<float4*>(sA + so + 8)  = va2;
            *reinterpret_cast<float4*>(sA + so + 12) = va3;
            *reinterpret_cast<float4*>(sB + so)      = vb0;
            *reinterpret_cast<float4*>(sB + so + 4)  = vb1;
            *reinterpret_cast<float4*>(sB + so + 8)  = vb2;
            *reinterpret_cast<float4*>(sB + so + 12) = vb3;
        }
        __syncthreads();
        #pragma unroll
        for (int s = 0; s < 4; s++) {     // four k8 steps in the 32-chunk
            const int k0 = s * 8;
            uint32_t ahi[4][4], alo[4][4];
            uint32_t bhi[2][4], blo[2][4];
            #pragma unroll
            for (int mt = 0; mt < 4; mt++) {
                uint32_t raw[4];
                uint32_t addr = aA + (uint32_t)(((warp_m * 64 + mt * 16 + frow) * STRIDE)
                                                + k0 + fcol) * 4u;
                ldsm4(raw, addr);
                #pragma unroll
                for (int q = 0; q < 4; q++) split_tf32(raw[q], ahi[mt][q], alo[mt][q]);
            }
            #pragma unroll
            for (int np = 0; np < 2; np++) {
                uint32_t raw[4];
                uint32_t addr = aB + (uint32_t)(((warp_n * 32 + np * 16 + frow) * STRIDE)
                                                + k0 + fcol) * 4u;
                ldsm4(raw, addr);
                #pragma unroll
                for (int q = 0; q < 4; q++) split_tf32(raw[q], bhi[np][q], blo[np][q]);
            }
            #pragma unroll
            for (int mt = 0; mt < 4; mt++)
                #pragma unroll
                for (int nt = 0; nt < 4; nt++) {
                    const int np = nt >> 1, g = nt & 1;
                    uint32_t bh[2] = {bhi[np][g], bhi[np][g + 2]};
                    uint32_t bl[2] = {blo[np][g], blo[np][g + 2]};
                    mma_tf32(acc[mt][nt], ahi[mt], bh);
                    mma_tf32(acc[mt][nt], ahi[mt], bl);
                    mma_tf32(acc[mt][nt], alo[mt], bh);
                }
        }
    }
}

// ---------------------------------------------------------------------------
// C[M,N] = A @ B^T + bias (split-tf32, ~fp32 accurate)
__global__ __launch_bounds__(256) void k_tgemm32(
    const float* __restrict__ A, const float* __restrict__ B,
    const float* __restrict__ bias, float* __restrict__ C,
    int ldc, int kdim)
{
    __shared__ __align__(16) float sA[128 * STRIDE];
    __shared__ __align__(16) float sB[128 * STRIDE];

    const int row0 = blockIdx.y * 128;
    const int col0 = blockIdx.x * 128;
    float acc[4][4][4];
    #pragma unroll
    for (int a = 0; a < 4; a++)
        #pragma unroll
        for (int b = 0; b < 4; b++)
            #pragma unroll
            for (int c = 0; c < 4; c++) acc[a][b][c] = 0.0f;

    gemm_core32(A, B, row0, col0, kdim, sA, sB, acc);

    const int lane = threadIdx.x & 31, wid = threadIdx.x >> 5;
    const int warp_m = wid >> 2, warp_n = wid & 3;
    const int tr = lane >> 2, tc = (lane & 3) * 2;
    #pragma unroll
    for (int mt = 0; mt < 4; mt++)
        #pragma unroll
        for (int h = 0; h < 2; h++) {
            int row = row0 + warp_m * 64 + mt * 16 + h * 8 + tr;
            #pragma unroll
            for (int nt = 0; nt < 4; nt++) {
                int col = col0 + warp_n * 32 + nt * 8 + tc;
                float v0 = acc[mt][nt][h * 2 + 0] + bias[col];
                float v1 = acc[mt][nt][h * 2 + 1] + bias[col + 1];
                *reinterpret_cast<float2*>(C + (size_t)row * ldc + col) = make_float2(v0, v1);
            }
        }
}

// ---------------------------------------------------------------------------
// Distance GEMM + argmin: cov = z @ cb^T ; d = sqr[k] - 2 cov ; atomicMin.
__global__ __launch_bounds__(256) void k_targmin32(const float* __restrict__ cb)
{
    __shared__ __align__(16) float sA[128 * STRIDE];
    __shared__ __align__(16) float sB[128 * STRIDE];

    const int row0  = blockIdx.y * 128;
    const int code0 = blockIdx.x * 128;
    float acc[4][4][4];
    #pragma unroll
    for (int a = 0; a < 4; a++)
        #pragma unroll
        for (int b = 0; b < 4; b++)
            #pragma unroll
            for (int c = 0; c < 4; c++) acc[a][b][c] = 0.0f;

    gemm_core32(g_z, cb, row0, code0, DEMB, sA, sB, acc);

    const int lane = threadIdx.x & 31, wid = threadIdx.x >> 5;
    const int warp_m = wid >> 2, warp_n = wid & 3;
    const int tr = lane >> 2, tc = (lane & 3) * 2;
    #pragma unroll
    for (int mt = 0; mt < 4; mt++)
        #pragma unroll
        for (int h = 0; h < 2; h++) {
            int row = row0 + warp_m * 64 + mt * 16 + h * 8 + tr;
            unsigned long long best = 0xFFFFFFFFFFFFFFFFull;
            #pragma unroll
            for (int nt = 0; nt < 4; nt++) {
                #pragma unroll
                for (int j = 0; j < 2; j++) {
                    int code = code0 + warp_n * 32 + nt * 8 + tc + j;
                    float d = fmaf(-2.0f, acc[mt][nt][h * 2 + j], g_sqr[code]);
                    unsigned u = __float_as_uint(d);
                    u = (u & 0x80000000u) ? ~u : (u | 0x80000000u);
                    unsigned long long pk = ((unsigned long long)u << 32) | (unsigned)code;
                    if (pk < best) best = pk;
                }
            }
            unsigned long long o1 = __shfl_xor_sync(0xffffffffu, best, 1);
            if (o1 < best) best = o1;
            unsigned long long o2 = __shfl_xor_sync(0xffffffffu, best, 2);
            if (o2 < best) best = o2;
            if ((lane & 3) == 0) atomicMin(&g_best[row], best);
        }
}

// ---------------------------------------------------------------------------
// fp32 transpose: dst[C,R] = src[R,C]^T ; id over R*C, write-coalesced.
__global__ void k_tr(const float* __restrict__ src, float* __restrict__ dst, int R, int C) {
    int id = blockIdx.x * blockDim.x + threadIdx.x;
    int c = id / R, r = id - c * R;
    dst[id] = src[(size_t)r * C + c];
}

// ---------------------------------------------------------------------------
__global__ void k_init() {
    int i = blockIdx.x * blockDim.x + threadIdx.x;
    if (i < KCB * DEMB) g_upd[i] = 0.0f;
    if (i < KCB)        g_cnt[i] = 0.0f;
    if (i < NROWS)      g_best[i] = 0xFFFFFFFFFFFFFFFFull;
    if (i == 0)         g_loss  = 0.0f;
}

__global__ void k_sqr(const float* __restrict__ cb) {
    int k = blockIdx.x, j = threadIdx.x;
    float v = cb[k * DEMB + j];
    float s = v * v;
    #pragma unroll
    for (int o = 16; o > 0; o >>= 1) s += __shfl_xor_sync(0xffffffffu, s, o);
    __shared__ float wsum[8];
    if ((j & 31) == 0) wsum[j >> 5] = s;
    __syncthreads();
    if (j == 0) {
        float tot = 0.0f;
        #pragma unroll
        for (int w = 0; w < 8; w++) tot += wsum[w];
        g_sqr[k] = tot;
    }
}

__global__ void k_codes(float* __restrict__ out) {
    int i = blockIdx.x * blockDim.x + threadIdx.x;
    if (i >= NROWS) return;
    unsigned long long p = g_best[i];
    int k = (int)(unsigned)(p & 0xFFFFFFFFull);
    unsigned ue = (unsigned)(p >> 32);
    float d = (ue & 0x80000000u) ? __uint_as_float(ue & 0x7FFFFFFFu)
                                 : __uint_as_float(~ue);
    g_codes[i] = k;
    g_dmin[i]  = d;
    out[OFF_CODES + i] = (float)k;
}

__global__ __launch_bounds__(256) void k_scatter() {
    int row  = blockIdx.x;
    int code = g_codes[row];
    int j    = threadIdx.x;
    float v  = g_z[(size_t)row * DEMB + j];
    atomicAdd(&g_upd[(size_t)code * DEMB + j], v);
    float sq = v * v;
    #pragma unroll
    for (int o = 16; o > 0; o >>= 1) sq += __shfl_xor_sync(0xffffffffu, sq, o);
    __shared__ float wsum[8];
    if ((j & 31) == 0) wsum[j >> 5] = sq;
    __syncthreads();
    if (j == 0) {
        float tot = 0.0f;
        #pragma unroll
        for (int w = 0; w < 8; w++) tot += wsum[w];
        atomicAdd(&g_loss, tot + g_dmin[row]);
        atomicAdd(&g_cnt[code], 1.0f);
    }
}

__global__ __launch_bounds__(1024) void k_final_small(
    const float* __restrict__ ema_size_in, float* __restrict__ out)
{
    __shared__ float sh[1024];
    int t = threadIdx.x;
    float cnt = g_cnt[t];
    float esz = ema_size_in[t] + ALPHA * (cnt - ema_size_in[t]);
    out[OFF_EMA_SIZE + t] = esz;

    sh[t] = esz;
    __syncthreads();
    for (int s = 512; s > 0; s >>= 1) {
        if (t < s) sh[t] += sh[t + s];
        __syncthreads();
    }
    float n = sh[0];
    __syncthreads();

    float coef = n / (n + (float)KCB * EPSV);
    g_size[t]  = coef * (esz + EPSV);

    float p = cnt * (1.0f / (float)NROWS);
    float e = (cnt > 0.0f) ? (-p * logf(p)) : 0.0f;
    sh[t] = e;
    __syncthreads();
    for (int s = 512; s > 0; s >>= 1) {
        if (t < s) sh[t] += sh[t + s];
        __syncthreads();
    }
    if (t == 0) {
        out[OFF_ENT]    = sh[0] / logf(2.0f);
        out[OFF_EMB]    = g_loss;
        out[OFF_COMMIT] = g_loss;
    }
}

__global__ void k_ema(const float* __restrict__ ema_vecs_in, float* __restrict__ out) {
    int i = blockIdx.x * blockDim.x + threadIdx.x;
    float v = ema_vecs_in[i] + ALPHA * (g_upd[i] - ema_vecs_in[i]);
    out[OFF_EMA_VECS + i] = v;
    out[OFF_WEIGHT + i]   = v / g_size[i >> 8];
}

__global__ __launch_bounds__(256) void k_gather(float* __restrict__ out) {
    int row  = blockIdx.x;
    int code = g_codes[row];
    const float4* src = reinterpret_cast<const float4*>(g_Y + (size_t)code * DIN);
    float4* dst = reinterpret_cast<float4*>(out + OFF_X + (size_t)row * DIN);
    dst[threadIdx.x] = src[threadIdx.x];
}

// ---------------------------------------------------------------------------
extern "C" void kernel_launch(void* const* d_in, const int* in_sizes, int n_in,
                              void* d_out, int out_size) {
    const float* input    = (const float*)d_in[0];
    const float* W_send   = (const float*)d_in[1];
    const float* b_send   = (const float*)d_in[2];
    const float* W_recv   = (const float*)d_in[3];
    const float* b_recv   = (const float*)d_in[4];
    const float* codebook = (const float*)d_in[5];
    const float* ema_vecs = (const float*)d_in[6];
    const float* ema_size = (const float*)d_in[7];
    float* out = (float*)d_out;

    float* z_ptr;   cudaGetSymbolAddress((void**)&z_ptr,   g_z);
    float* Y_ptr;   cudaGetSymbolAddress((void**)&Y_ptr,   g_Y);
    float* wsT_ptr; cudaGetSymbolAddress((void**)&wsT_ptr, g_wsT);
    float* wrT_ptr; cudaGetSymbolAddress((void**)&wrT_ptr, g_wrT);

    k_init<<<1024, 256>>>();
    k_sqr<<<KCB, 256>>>(codebook);
    // fp32 transposes of the two weight matrices
    k_tr<<<DIN * DEMB / 256, 256>>>(W_send, wsT_ptr, DIN, DEMB);   // -> [256,1024]
    k_tr<<<DIN * DEMB / 256, 256>>>(W_recv, wrT_ptr, DEMB, DIN);   // -> [1024,256]
    // z = input @ W_send + b_send : M=16384, N=256, K=1024 (3xTF32)
    k_tgemm32<<<dim3(2, 128), 256>>>(input, wsT_ptr, b_send, z_ptr, DEMB, DIN);
    // Y = codebook @ W_recv + b_recv : M=1024, N=1024, K=256 (3xTF32)
    k_tgemm32<<<dim3(8, 8), 256>>>(codebook, wrT_ptr, b_recv, Y_ptr, DIN, DEMB);
    // argmin over 128x128 tiles (3xTF32 distances, fp32-faithful)
    k_targmin32<<<dim3(8, 128), 256>>>(codebook);
    k_codes<<<64, 256>>>(out);
    k_scatter<<<NROWS, 256>>>();
    k_final_small<<<1, 1024>>>(ema_size, out);
    k_ema<<<1024, 256>>>(ema_vecs, out);
    k_gather<<<NROWS, 256>>>(out);
}

// round 6
// speedup vs baseline: 1.4683x; 1.0056x over previous
#include <cuda_runtime.h>
#include <cuda_bf16.h>
#include <math.h>
#include <stdint.h>

// Problem constants
#define NROWS 16384
#define DIN   1024
#define DEMB  256
#define KCB   1024
#define ALPHA 0.01f
#define EPSV  1e-5f
#define MARGIN 4.0f

// Output layout (float32, tuple order concatenated)
#define OFF_X        ((size_t)0)
#define OFF_CODES    ((size_t)16777216)
#define OFF_EMB      ((size_t)16793600)
#define OFF_COMMIT   ((size_t)16793601)
#define OFF_ENT      ((size_t)16793602)
#define OFF_EMA_VECS ((size_t)16793603)
#define OFF_EMA_SIZE ((size_t)17055747)
#define OFF_WEIGHT   ((size_t)17056771)

// ---------------------------------------------------------------------------
// Scratch (device globals; no allocations allowed)
__device__ float g_z[NROWS * DEMB];
__device__ float g_sqr[KCB];
__device__ int   g_codes[NROWS];
__device__ float g_dmin[NROWS];
__device__ float g_upd[KCB * DEMB];
__device__ float g_cnt[KCB];
__device__ float g_loss;
__device__ float g_size[KCB];
__device__ float g_Y[KCB * DIN];
__device__ float g_cov[NROWS * KCB];           // 64 MB approx cov
__device__ float g_wsT_hi[DEMB * DIN], g_wsT_lo[DEMB * DIN];  // tf32 split W_send^T
__device__ float g_wrT_hi[DIN * DEMB], g_wrT_lo[DIN * DEMB];  // tf32 split W_recv^T
__device__ __nv_bfloat16 g_zh[NROWS * DEMB], g_zl[NROWS * DEMB];
__device__ __nv_bfloat16 g_cb_hi[KCB * DEMB], g_cb_lo[KCB * DEMB];

// ---------------------------------------------------------------------------
__device__ __forceinline__ uint32_t smem_u32(const void* p) {
    uint32_t a;
    asm("{ .reg .u64 t; cvta.to.shared.u64 t, %1; cvt.u32.u64 %0, t; }" : "=r"(a) : "l"(p));
    return a;
}
__device__ __forceinline__ void ldsm4(uint32_t* r, uint32_t addr) {
    asm volatile("ldmatrix.sync.aligned.m8n8.x4.shared.b16 {%0,%1,%2,%3}, [%4];"
                 : "=r"(r[0]), "=r"(r[1]), "=r"(r[2]), "=r"(r[3]) : "r"(addr));
}
__device__ __forceinline__ void mma_tf32(float* c, const uint32_t* a, const uint32_t* b) {
    asm volatile("mma.sync.aligned.m16n8k8.row.col.f32.tf32.tf32.f32 "
                 "{%0,%1,%2,%3}, {%4,%5,%6,%7}, {%8,%9}, {%0,%1,%2,%3};"
                 : "+f"(c[0]), "+f"(c[1]), "+f"(c[2]), "+f"(c[3])
                 : "r"(a[0]), "r"(a[1]), "r"(a[2]), "r"(a[3]), "r"(b[0]), "r"(b[1]));
}
__device__ __forceinline__ void mma_bf16(float* c, const uint32_t* a, const uint32_t* b) {
    asm volatile("mma.sync.aligned.m16n8k16.row.col.f32.bf16.bf16.f32 "
                 "{%0,%1,%2,%3}, {%4,%5,%6,%7}, {%8,%9}, {%0,%1,%2,%3};"
                 : "+f"(c[0]), "+f"(c[1]), "+f"(c[2]), "+f"(c[3])
                 : "r"(a[0]), "r"(a[1]), "r"(a[2]), "r"(a[3]), "r"(b[0]), "r"(b[1]));
}
__device__ __forceinline__ uint32_t f2tf32(float x) {
    uint32_t r;
    asm("cvt.rna.tf32.f32 %0, %1;" : "=r"(r) : "f"(x));
    return r;
}
__device__ __forceinline__ void split_tf32(uint32_t raw, uint32_t& hi, uint32_t& lo) {
    float x = __uint_as_float(raw);
    hi = f2tf32(x);
    lo = f2tf32(x - __uint_as_float(hi));
}

#define STRIDE 36       // fp32 units / smem row (tf32 kernel)
#define BSTRIDE 40      // bf16 units / smem row (cov kernel)

// ===========================================================================
// 3xTF32 GEMM, B pre-split (hi/lo fp32 arrays), A split in-register.
// CTA 128x128, K chunks of 32. 8 warps 2x4, warp 64x32, m16n8k8.
__global__ __launch_bounds__(256) void k_tgemm32(
    const float* __restrict__ A,
    const float* __restrict__ Bh, const float* __restrict__ Bl,
    const float* __restrict__ bias, float* __restrict__ C,
    __nv_bfloat16* __restrict__ Chi, __nv_bfloat16* __restrict__ Clo,
    int ldc, int kdim, int write_bf16)
{
    __shared__ __align__(16) float sA[128 * STRIDE];
    __shared__ __align__(16) float sBh[128 * STRIDE];
    __shared__ __align__(16) float sBl[128 * STRIDE];

    const int tid  = threadIdx.x;
    const int lane = tid & 31;
    const int wid  = tid >> 5;
    const int warp_m = wid >> 2, warp_n = wid & 3;
    const int row0 = blockIdx.y * 128;
    const int col0 = blockIdx.x * 128;

    const uint32_t aA = smem_u32(sA), aBh = smem_u32(sBh), aBl = smem_u32(sBl);
    const int r = tid >> 1, cshift = (tid & 1) * 16;
    const int frow = lane & 15, fcol = (lane >> 4) * 4;

    float acc[4][4][4];
    #pragma unroll
    for (int a = 0; a < 4; a++)
        #pragma unroll
        for (int b = 0; b < 4; b++)
            #pragma unroll
            for (int c = 0; c < 4; c++) acc[a][b][c] = 0.0f;

    for (int kc = 0; kc < kdim; kc += 32) {
        __syncthreads();
        {
            size_t ga = (size_t)(row0 + r) * kdim + kc + cshift;
            size_t gb = (size_t)(col0 + r) * kdim + kc + cshift;
            int so = r * STRIDE + cshift;
            #pragma unroll
            for (int q = 0; q < 4; q++)
                *reinterpret_cast<float4*>(sA + so + 4 * q) =
                    *reinterpret_cast<const float4*>(A + ga + 4 * q);
            #pragma unroll
            for (int q = 0; q < 4; q++)
                *reinterpret_cast<float4*>(sBh + so + 4 * q) =
                    *reinterpret_cast<const float4*>(Bh + gb + 4 * q);
            #pragma unroll
            for (int q = 0; q < 4; q++)
                *reinterpret_cast<float4*>(sBl + so + 4 * q) =
                    *reinterpret_cast<const float4*>(Bl + gb + 4 * q);
        }
        __syncthreads();
        #pragma unroll
        for (int s = 0; s < 4; s++) {
            const int k0 = s * 8;
            uint32_t ahi[4][4], alo[4][4], bh[2][4], bl[2][4];
            #pragma unroll
            for (int mt = 0; mt < 4; mt++) {
                uint32_t raw[4];
                uint32_t addr = aA + (uint32_t)(((warp_m * 64 + mt * 16 + frow) * STRIDE)
                                                + k0 + fcol) * 4u;
                ldsm4(raw, addr);
                #pragma unroll
                for (int q = 0; q < 4; q++) split_tf32(raw[q], ahi[mt][q], alo[mt][q]);
            }
            #pragma unroll
            for (int np = 0; np < 2; np++) {
                uint32_t off = (uint32_t)(((warp_n * 32 + np * 16 + frow) * STRIDE)
                                          + k0 + fcol) * 4u;
                ldsm4(bh[np], aBh + off);
                ldsm4(bl[np], aBl + off);
            }
            #pragma unroll
            for (int mt = 0; mt < 4; mt++)
                #pragma unroll
                for (int nt = 0; nt < 4; nt++) {
                    const int np = nt >> 1, g = nt & 1;
                    uint32_t vh[2] = {bh[np][g], bh[np][g + 2]};
                    uint32_t vl[2] = {bl[np][g], bl[np][g + 2]};
                    mma_tf32(acc[mt][nt], ahi[mt], vh);
                    mma_tf32(acc[mt][nt], ahi[mt], vl);
                    mma_tf32(acc[mt][nt], alo[mt], vh);
                }
        }
    }

    const int tr = lane >> 2, tc = (lane & 3) * 2;
    #pragma unroll
    for (int mt = 0; mt < 4; mt++)
        #pragma unroll
        for (int h = 0; h < 2; h++) {
            int row = row0 + warp_m * 64 + mt * 16 + h * 8 + tr;
            #pragma unroll
            for (int nt = 0; nt < 4; nt++) {
                int col = col0 + warp_n * 32 + nt * 8 + tc;
                float v0 = acc[mt][nt][h * 2 + 0] + bias[col];
                float v1 = acc[mt][nt][h * 2 + 1] + bias[col + 1];
                size_t o = (size_t)row * ldc + col;
                *reinterpret_cast<float2*>(C + o) = make_float2(v0, v1);
                if (write_bf16) {
                    __nv_bfloat162 hp = __floats2bfloat162_rn(v0, v1);
                    __nv_bfloat162 lp = __floats2bfloat162_rn(
                        v0 - __bfloat162float(hp.x), v1 - __bfloat162float(hp.y));
                    *reinterpret_cast<uint32_t*>(Chi + o) = *reinterpret_cast<uint32_t*>(&hp);
                    *reinterpret_cast<uint32_t*>(Clo + o) = *reinterpret_cast<uint32_t*>(&lp);
                }
            }
        }
}

// ===========================================================================
// Pass A: bf16x3 cov GEMM. cov[n,k] = z_n . cb_k (error <= ~0.3 abs).
__global__ __launch_bounds__(256) void k_cov()
{
    __shared__ __align__(16) __nv_bfloat16 sAh[128 * BSTRIDE];
    __shared__ __align__(16) __nv_bfloat16 sAl[128 * BSTRIDE];
    __shared__ __align__(16) __nv_bfloat16 sBh[128 * BSTRIDE];
    __shared__ __align__(16) __nv_bfloat16 sBl[128 * BSTRIDE];

    const int tid  = threadIdx.x;
    const int lane = tid & 31;
    const int wid  = tid >> 5;
    const int warp_m = wid >> 2, warp_n = wid & 3;
    const int row0  = blockIdx.y * 128;
    const int code0 = blockIdx.x * 128;

    const uint32_t aAh = smem_u32(sAh), aAl = smem_u32(sAl);
    const uint32_t aBh = smem_u32(sBh), aBl = smem_u32(sBl);
    const int r = tid >> 1, cshift = (tid & 1) * 16;

    const int arow = warp_m * 64 + (lane & 15);
    const int acol_h = (lane >> 4) * 8;
    const int quad = lane >> 3;
    const int brow = warp_n * 32 + ((quad >> 1) * 8) + (lane & 7);
    const int bcol_h = (quad & 1) * 8;

    float acc[4][4][4];
    #pragma unroll
    for (int a = 0; a < 4; a++)
        #pragma unroll
        for (int b = 0; b < 4; b++)
            #pragma unroll
            for (int c = 0; c < 4; c++) acc[a][b][c] = 0.0f;

    for (int kc = 0; kc < DEMB; kc += 32) {
        __syncthreads();
        {
            size_t ga = (size_t)(row0 + r) * DEMB + kc + cshift;
            size_t gb = (size_t)(code0 + r) * DEMB + kc + cshift;
            int so = r * BSTRIDE + cshift;
            *reinterpret_cast<uint4*>(sAh + so)     = *reinterpret_cast<const uint4*>(g_zh + ga);
            *reinterpret_cast<uint4*>(sAh + so + 8) = *reinterpret_cast<const uint4*>(g_zh + ga + 8);
            *reinterpret_cast<uint4*>(sAl + so)     = *reinterpret_cast<const uint4*>(g_zl + ga);
            *reinterpret_cast<uint4*>(sAl + so + 8) = *reinterpret_cast<const uint4*>(g_zl + ga + 8);
            *reinterpret_cast<uint4*>(sBh + so)     = *reinterpret_cast<const uint4*>(g_cb_hi + gb);
            *reinterpret_cast<uint4*>(sBh + so + 8) = *reinterpret_cast<const uint4*>(g_cb_hi + gb + 8);
            *reinterpret_cast<uint4*>(sBl + so)     = *reinterpret_cast<const uint4*>(g_cb_lo + gb);
            *reinterpret_cast<uint4*>(sBl + so + 8) = *reinterpret_cast<const uint4*>(g_cb_lo + gb + 8);
        }
        __syncthreads();
        #pragma unroll
        for (int ks = 0; ks < 2; ks++) {
            const int k0 = ks * 16;
            uint32_t ah[4][4], al[4][4], bh[2][4], bl[2][4];
            #pragma unroll
            for (int mt = 0; mt < 4; mt++) {
                uint32_t off = (uint32_t)(((arow + mt * 16) * BSTRIDE) + k0 + acol_h) * 2;
                ldsm4(ah[mt], aAh + off);
                ldsm4(al[mt], aAl + off);
            }
            #pragma unroll
            for (int np = 0; np < 2; np++) {
                uint32_t off = (uint32_t)(((brow + np * 16) * BSTRIDE) + k0 + bcol_h) * 2;
                ldsm4(bh[np], aBh + off);
                ldsm4(bl[np], aBl + off);
            }
            #pragma unroll
            for (int mt = 0; mt < 4; mt++)
                #pragma unroll
                for (int nt = 0; nt < 4; nt++) {
                    const uint32_t* bhp = &bh[nt >> 1][(nt & 1) * 2];
                    const uint32_t* blp = &bl[nt >> 1][(nt & 1) * 2];
                    mma_bf16(acc[mt][nt], ah[mt], bhp);
                    mma_bf16(acc[mt][nt], ah[mt], blp);
                    mma_bf16(acc[mt][nt], al[mt], bhp);
                }
        }
    }

    const int tr = lane >> 2, tc = (lane & 3) * 2;
    #pragma unroll
    for (int mt = 0; mt < 4; mt++)
        #pragma unroll
        for (int h = 0; h < 2; h++) {
            int row = row0 + warp_m * 64 + mt * 16 + h * 8 + tr;
            #pragma unroll
            for (int nt = 0; nt < 4; nt++) {
                int col = code0 + warp_n * 32 + nt * 8 + tc;
                *reinterpret_cast<float2*>(g_cov + (size_t)row * KCB + col) =
                    make_float2(acc[mt][nt][h * 2], acc[mt][nt][h * 2 + 1]);
            }
        }
}

// ===========================================================================
// Pass B: exact refine. Per row: approx min, candidates within MARGIN,
// exact fp32 distance for candidates, winner (tie -> lowest code).
__global__ __launch_bounds__(256) void k_refine(
    const float* __restrict__ cb, float* __restrict__ out)
{
    __shared__ float s_z[DEMB];
    __shared__ float s_red[256];
    __shared__ int   s_cand[64];
    __shared__ int   s_ncand;
    __shared__ unsigned long long s_best;

    const int row = blockIdx.x;
    const int t = threadIdx.x;
    const int wid = t >> 5, lane = t & 31;

    s_z[t] = g_z[(size_t)row * DEMB + t];
    if (t == 0) { s_ncand = 0; s_best = 0xFFFFFFFFFFFFFFFFull; }

    float dt[4];
    float lm = 3.4e38f;
    #pragma unroll
    for (int i = 0; i < 4; i++) {
        int c = i * 256 + t;
        dt[i] = fmaf(-2.0f, g_cov[(size_t)row * KCB + c], g_sqr[c]);
        lm = fminf(lm, dt[i]);
    }
    s_red[t] = lm;
    __syncthreads();
    for (int s = 128; s > 0; s >>= 1) {
        if (t < s) s_red[t] = fminf(s_red[t], s_red[t + s]);
        __syncthreads();
    }
    const float thr = s_red[0] + MARGIN;
    __syncthreads();

    #pragma unroll
    for (int i = 0; i < 4; i++) {
        if (dt[i] <= thr) {
            int idx = atomicAdd(&s_ncand, 1);
            if (idx < 64) s_cand[idx] = i * 256 + t;
        }
    }
    __syncthreads();
    const int nc = s_ncand;

    if (nc <= 64) {
        for (int ci = wid; ci < nc; ci += 8) {
            int c = s_cand[ci];
            const float* cbr = cb + (size_t)c * DEMB;
            float dot = 0.0f;
            #pragma unroll
            for (int j = 0; j < 8; j++) dot = fmaf(s_z[lane + 32 * j], cbr[lane + 32 * j], dot);
            #pragma unroll
            for (int o = 16; o > 0; o >>= 1) dot += __shfl_xor_sync(0xffffffffu, dot, o);
            if (lane == 0) {
                float d = fmaf(-2.0f, dot, g_sqr[c]);
                unsigned u = __float_as_uint(d);
                u = (u & 0x80000000u) ? ~u : (u | 0x80000000u);
                atomicMin(&s_best, ((unsigned long long)u << 32) | (unsigned)c);
            }
        }
    } else {
        // fallback: exact scan of all codes (never expected)
        for (int c = wid; c < KCB; c += 8) {
            const float* cbr = cb + (size_t)c * DEMB;
            float dot = 0.0f;
            #pragma unroll
            for (int j = 0; j < 8; j++) dot = fmaf(s_z[lane + 32 * j], cbr[lane + 32 * j], dot);
            #pragma unroll
            for (int o = 16; o > 0; o >>= 1) dot += __shfl_xor_sync(0xffffffffu, dot, o);
            if (lane == 0) {
                float d = fmaf(-2.0f, dot, g_sqr[c]);
                unsigned u = __float_as_uint(d);
                u = (u & 0x80000000u) ? ~u : (u | 0x80000000u);
                atomicMin(&s_best, ((unsigned long long)u << 32) | (unsigned)c);
            }
        }
    }
    __syncthreads();
    if (t == 0) {
        unsigned long long p = s_best;
        int k = (int)(unsigned)(p & 0xFFFFFFFFull);
        unsigned ue = (unsigned)(p >> 32);
        float d = (ue & 0x80000000u) ? __uint_as_float(ue & 0x7FFFFFFFu)
                                     : __uint_as_float(~ue);
        g_codes[row] = k;
        g_dmin[row]  = d;
        out[OFF_CODES + row] = (float)k;
    }
}

// ===========================================================================
// transpose + tf32 hi/lo split: dst[C,R] = split(src[R,C]^T)
__global__ void k_trsplit(const float* __restrict__ src, float* __restrict__ hi,
                          float* __restrict__ lo, int R, int C) {
    int id = blockIdx.x * blockDim.x + threadIdx.x;
    int c = id / R, r = id - c * R;
    float v = src[(size_t)r * C + c];
    uint32_t h = f2tf32(v);
    float hf = __uint_as_float(h);
    hi[id] = hf;
    lo[id] = __uint_as_float(f2tf32(v - hf));
}

// codebook -> bf16 hi/lo
__global__ void k_convcb(const float* __restrict__ src, __nv_bfloat16* __restrict__ hi,
                         __nv_bfloat16* __restrict__ lo) {
    size_t i = ((size_t)blockIdx.x * blockDim.x + threadIdx.x) * 4;
    float4 v = *reinterpret_cast<const float4*>(src + i);
    __nv_bfloat162 h01 = __floats2bfloat162_rn(v.x, v.y);
    __nv_bfloat162 h23 = __floats2bfloat162_rn(v.z, v.w);
    __nv_bfloat162 l01 = __floats2bfloat162_rn(v.x - __bfloat162float(h01.x),
                                               v.y - __bfloat162float(h01.y));
    __nv_bfloat162 l23 = __floats2bfloat162_rn(v.z - __bfloat162float(h23.x),
                                               v.w - __bfloat162float(h23.y));
    uint2 hp, lp;
    hp.x = *reinterpret_cast<uint32_t*>(&h01); hp.y = *reinterpret_cast<uint32_t*>(&h23);
    lp.x = *reinterpret_cast<uint32_t*>(&l01); lp.y = *reinterpret_cast<uint32_t*>(&l23);
    *reinterpret_cast<uint2*>(hi + i) = hp;
    *reinterpret_cast<uint2*>(lo + i) = lp;
}

// ---------------------------------------------------------------------------
__global__ void k_init() {
    int i = blockIdx.x * blockDim.x + threadIdx.x;
    if (i < KCB * DEMB) g_upd[i] = 0.0f;
    if (i < KCB)        g_cnt[i] = 0.0f;
    if (i == 0)         g_loss  = 0.0f;
}

__global__ void k_sqr(const float* __restrict__ cb) {
    int k = blockIdx.x, j = threadIdx.x;
    float v = cb[k * DEMB + j];
    float s = v * v;
    #pragma unroll
    for (int o = 16; o > 0; o >>= 1) s += __shfl_xor_sync(0xffffffffu, s, o);
    __shared__ float wsum[8];
    if ((j & 31) == 0) wsum[j >> 5] = s;
    __syncthreads();
    if (j == 0) {
        float tot = 0.0f;
        #pragma unroll
        for (int w = 0; w < 8; w++) tot += wsum[w];
        g_sqr[k] = tot;
    }
}

__global__ __launch_bounds__(256) void k_scatter() {
    int row  = blockIdx.x;
    int code = g_codes[row];
    int j    = threadIdx.x;
    float v  = g_z[(size_t)row * DEMB + j];
    atomicAdd(&g_upd[(size_t)code * DEMB + j], v);
    float sq = v * v;
    #pragma unroll
    for (int o = 16; o > 0; o >>= 1) sq += __shfl_xor_sync(0xffffffffu, sq, o);
    __shared__ float wsum[8];
    if ((j & 31) == 0) wsum[j >> 5] = sq;
    __syncthreads();
    if (j == 0) {
        float tot = 0.0f;
        #pragma unroll
        for (int w = 0; w < 8; w++) tot += wsum[w];
        atomicAdd(&g_loss, tot + g_dmin[row]);
        atomicAdd(&g_cnt[code], 1.0f);
    }
}

__global__ __launch_bounds__(1024) void k_final_small(
    const float* __restrict__ ema_size_in, float* __restrict__ out)
{
    __shared__ float sh[1024];
    int t = threadIdx.x;
    float cnt = g_cnt[t];
    float esz = ema_size_in[t] + ALPHA * (cnt - ema_size_in[t]);
    out[OFF_EMA_SIZE + t] = esz;

    sh[t] = esz;
    __syncthreads();
    for (int s = 512; s > 0; s >>= 1) {
        if (t < s) sh[t] += sh[t + s];
        __syncthreads();
    }
    float n = sh[0];
    __syncthreads();

    float coef = n / (n + (float)KCB * EPSV);
    g_size[t]  = coef * (esz + EPSV);

    float p = cnt * (1.0f / (float)NROWS);
    float e = (cnt > 0.0f) ? (-p * logf(p)) : 0.0f;
    sh[t] = e;
    __syncthreads();
    for (int s = 512; s > 0; s >>= 1) {
        if (t < s) sh[t] += sh[t + s];
        __syncthreads();
    }
    if (t == 0) {
        out[OFF_ENT]    = sh[0] / logf(2.0f);
        out[OFF_EMB]    = g_loss;
        out[OFF_COMMIT] = g_loss;
    }
}

__global__ void k_ema(const float* __restrict__ ema_vecs_in, float* __restrict__ out) {
    int i = blockIdx.x * blockDim.x + threadIdx.x;
    float v = ema_vecs_in[i] + ALPHA * (g_upd[i] - ema_vecs_in[i]);
    out[OFF_EMA_VECS + i] = v;
    out[OFF_WEIGHT + i]   = v / g_size[i >> 8];
}

__global__ __launch_bounds__(256) void k_gather(float* __restrict__ out) {
    int row  = blockIdx.x;
    int code = g_codes[row];
    const float4* src = reinterpret_cast<const float4*>(g_Y + (size_t)code * DIN);
    float4* dst = reinterpret_cast<float4*>(out + OFF_X + (size_t)row * DIN);
    dst[threadIdx.x] = src[threadIdx.x];
}

// ---------------------------------------------------------------------------
extern "C" void kernel_launch(void* const* d_in, const int* in_sizes, int n_in,
                              void* d_out, int out_size) {
    const float* input    = (const float*)d_in[0];
    const float* W_send   = (const float*)d_in[1];
    const float* b_send   = (const float*)d_in[2];
    const float* W_recv   = (const float*)d_in[3];
    const float* b_recv   = (const float*)d_in[4];
    const float* codebook = (const float*)d_in[5];
    const float* ema_vecs = (const float*)d_in[6];
    const float* ema_size = (const float*)d_in[7];
    float* out = (float*)d_out;

    float *z_ptr, *Y_ptr, *wsh, *wsl, *wrh, *wrl;
    __nv_bfloat16 *zh, *zl, *cbh, *cbl;
    cudaGetSymbolAddress((void**)&z_ptr, g_z);
    cudaGetSymbolAddress((void**)&Y_ptr, g_Y);
    cudaGetSymbolAddress((void**)&wsh, g_wsT_hi); cudaGetSymbolAddress((void**)&wsl, g_wsT_lo);
    cudaGetSymbolAddress((void**)&wrh, g_wrT_hi); cudaGetSymbolAddress((void**)&wrl, g_wrT_lo);
    cudaGetSymbolAddress((void**)&zh, g_zh);      cudaGetSymbolAddress((void**)&zl, g_zl);
    cudaGetSymbolAddress((void**)&cbh, g_cb_hi);  cudaGetSymbolAddress((void**)&cbl, g_cb_lo);

    k_init<<<1024, 256>>>();
    k_sqr<<<KCB, 256>>>(codebook);
    k_trsplit<<<DIN * DEMB / 256, 256>>>(W_send, wsh, wsl, DIN, DEMB);  // -> [256,1024]
    k_trsplit<<<DIN * DEMB / 256, 256>>>(W_recv, wrh, wrl, DEMB, DIN);  // -> [1024,256]
    k_convcb<<<KCB * DEMB / 1024, 256>>>(codebook, cbh, cbl);
    // z = input @ W_send + b_send (3xTF32, fused bf16 z split out)
    k_tgemm32<<<dim3(2, 128), 256>>>(input, wsh, wsl, b_send, z_ptr, zh, zl, DEMB, DIN, 1);
    // Y = codebook @ W_recv + b_recv (3xTF32)
    k_tgemm32<<<dim3(8, 8), 256>>>(codebook, wrh, wrl, b_recv, Y_ptr,
                                   (__nv_bfloat16*)nullptr, (__nv_bfloat16*)nullptr,
                                   DIN, DEMB, 0);
    // Pass A: approximate cov (bf16x3), Pass B: exact refine -> codes
    k_cov<<<dim3(8, 128), 256>>>();
    k_refine<<<NROWS, 256>>>(codebook, out);
    k_scatter<<<NROWS, 256>>>();
    k_final_small<<<1, 1024>>>(ema_size, out);
    k_ema<<<1024, 256>>>(ema_vecs, out);
    k_gather<<<NROWS, 256>>>(out);
}

// round 8
// speedup vs baseline: 2.2129x; 1.5071x over previous
#include <cuda_runtime.h>
#include <cuda_bf16.h>
#include <math.h>
#include <stdint.h>

// Problem constants
#define NROWS 16384
#define DIN   1024
#define DEMB  256
#define KCB   1024
#define ALPHA 0.01f
#define EPSV  1e-5f
#define MARGIN 4.0f

// Output layout (float32, tuple order concatenated)
#define OFF_X        ((size_t)0)
#define OFF_CODES    ((size_t)16777216)
#define OFF_EMB      ((size_t)16793600)
#define OFF_COMMIT   ((size_t)16793601)
#define OFF_ENT      ((size_t)16793602)
#define OFF_EMA_VECS ((size_t)16793603)
#define OFF_EMA_SIZE ((size_t)17055747)
#define OFF_WEIGHT   ((size_t)17056771)

// ---------------------------------------------------------------------------
// Scratch (device globals; no allocations allowed)
__device__ float g_z[NROWS * DEMB];
__device__ float g_sqr[KCB];
__device__ int   g_codes[NROWS];
__device__ float g_dmin[NROWS];
__device__ float g_upd[KCB * DEMB];
__device__ float g_cnt[KCB];
__device__ float g_loss;
__device__ float g_size[KCB];
__device__ float g_Y[KCB * DIN];
__device__ float g_cov[NROWS * KCB];          // 64 MB approx cov (single bf16)
__device__ float g_wsT_hi[DEMB * DIN], g_wsT_lo[DEMB * DIN];
__device__ float g_wrT_hi[DIN * DEMB], g_wrT_lo[DIN * DEMB];
__device__ __nv_bfloat16 g_zh[NROWS * DEMB];
__device__ __nv_bfloat16 g_cbh[KCB * DEMB];

// ---------------------------------------------------------------------------
__device__ __forceinline__ uint32_t smem_u32(const void* p) {
    uint32_t a;
    asm("{ .reg .u64 t; cvta.to.shared.u64 t, %1; cvt.u32.u64 %0, t; }" : "=r"(a) : "l"(p));
    return a;
}
__device__ __forceinline__ void ldsm4(uint32_t* r, uint32_t addr) {
    asm volatile("ldmatrix.sync.aligned.m8n8.x4.shared.b16 {%0,%1,%2,%3}, [%4];"
                 : "=r"(r[0]), "=r"(r[1]), "=r"(r[2]), "=r"(r[3]) : "r"(addr));
}
__device__ __forceinline__ void mma_tf32(float* c, const uint32_t* a, const uint32_t* b) {
    asm volatile("mma.sync.aligned.m16n8k8.row.col.f32.tf32.tf32.f32 "
                 "{%0,%1,%2,%3}, {%4,%5,%6,%7}, {%8,%9}, {%0,%1,%2,%3};"
                 : "+f"(c[0]), "+f"(c[1]), "+f"(c[2]), "+f"(c[3])
                 : "r"(a[0]), "r"(a[1]), "r"(a[2]), "r"(a[3]), "r"(b[0]), "r"(b[1]));
}
__device__ __forceinline__ void mma_bf16(float* c, const uint32_t* a, const uint32_t* b) {
    asm volatile("mma.sync.aligned.m16n8k16.row.col.f32.bf16.bf16.f32 "
                 "{%0,%1,%2,%3}, {%4,%5,%6,%7}, {%8,%9}, {%0,%1,%2,%3};"
                 : "+f"(c[0]), "+f"(c[1]), "+f"(c[2]), "+f"(c[3])
                 : "r"(a[0]), "r"(a[1]), "r"(a[2]), "r"(a[3]), "r"(b[0]), "r"(b[1]));
}
__device__ __forceinline__ uint32_t f2tf32(float x) {
    uint32_t r;
    asm("cvt.rna.tf32.f32 %0, %1;" : "=r"(r) : "f"(x));
    return r;
}
#define CP16(sm, gp) asm volatile("cp.async.ca.shared.global [%0], [%1], 16;" :: "r"(sm), "l"(gp))
#define CPCOMMIT()   asm volatile("cp.async.commit_group;" ::: "memory")
#define CPWAIT0()    asm volatile("cp.async.wait_group 0;" ::: "memory")
#define CPWAIT1()    asm volatile("cp.async.wait_group 1;" ::: "memory")

// ===========================================================================
// 3xTF32 GEMM: C = A @ B^T + bias. A fp32 (split in-register), B pre-split.
// CTA 128x128, BK=32, cp.async 2-stage. 8 warps 4(m)x2(n), warp 32x64.
#define ZSTRIDE 36
#define ZARR (128 * ZSTRIDE)          // floats per array
#define ZSTAGE (3 * ZARR)
#define ZSMEM_BYTES (2 * ZSTAGE * 4)  // 110592

__device__ __forceinline__ void z_loads(uint32_t sbase, int buf,
    const float* __restrict__ A, const float* __restrict__ Bh,
    const float* __restrict__ Bl, int row0, int col0, int kdim, int kc, int tid)
{
    #pragma unroll
    for (int t = 0; t < 4; t++) {
        int seg = tid + t * 256;
        int rr = seg >> 3, cc = (seg & 7) * 4;
        uint32_t so = sbase + (uint32_t)(buf * ZSTAGE + rr * ZSTRIDE + cc) * 4u;
        CP16(so,                  A  + (size_t)(row0 + rr) * kdim + kc + cc);
        CP16(so + ZARR * 4u,      Bh + (size_t)(col0 + rr) * kdim + kc + cc);
        CP16(so + 2u * ZARR * 4u, Bl + (size_t)(col0 + rr) * kdim + kc + cc);
    }
    CPCOMMIT();
}

__global__ __launch_bounds__(256, 2) void k_tgemm32(
    const float* __restrict__ A,
    const float* __restrict__ Bh, const float* __restrict__ Bl,
    const float* __restrict__ bias, float* __restrict__ C,
    __nv_bfloat16* __restrict__ Chi, int ldc, int kdim, int write_bf)
{
    extern __shared__ float dsm[];
    const int tid = threadIdx.x, lane = tid & 31, wid = tid >> 5;
    const int warp_m = wid & 3, warp_n = wid >> 2;
    const int row0 = blockIdx.y * 128, col0 = blockIdx.x * 128;
    const int frow = lane & 15, fcol = (lane >> 4) * 4;
    const uint32_t sbase = smem_u32(dsm);

    float acc[2][8][4];
    #pragma unroll
    for (int a = 0; a < 2; a++)
        #pragma unroll
        for (int b = 0; b < 8; b++)
            #pragma unroll
            for (int c = 0; c < 4; c++) acc[a][b][c] = 0.0f;

    const int nch = kdim >> 5;
    z_loads(sbase, 0, A, Bh, Bl, row0, col0, kdim, 0, tid);

    for (int c = 0; c < nch; c++) {
        if (c + 1 < nch) {
            z_loads(sbase, (c + 1) & 1, A, Bh, Bl, row0, col0, kdim, (c + 1) * 32, tid);
            CPWAIT1();
        } else {
            CPWAIT0();
        }
        __syncthreads();
        const uint32_t sb = sbase + (uint32_t)((c & 1) * ZSTAGE) * 4u;
        #pragma unroll
        for (int s = 0; s < 4; s++) {
            const int k0 = s * 8;
            uint32_t ahi[2][4], alo[2][4], bh[4][4], bl[4][4];
            #pragma unroll
            for (int mt = 0; mt < 2; mt++) {
                uint32_t raw[4];
                ldsm4(raw, sb + (uint32_t)(((warp_m * 32 + mt * 16 + frow) * ZSTRIDE)
                                           + k0 + fcol) * 4u);
                #pragma unroll
                for (int q = 0; q < 4; q++) {
                    float x = __uint_as_float(raw[q]);
                    ahi[mt][q] = f2tf32(x);
                    alo[mt][q] = f2tf32(x - __uint_as_float(ahi[mt][q]));
                }
            }
            #pragma unroll
            for (int np = 0; np < 4; np++) {
                uint32_t off = (uint32_t)(((warp_n * 64 + np * 16 + frow) * ZSTRIDE)
                                          + k0 + fcol) * 4u;
                ldsm4(bh[np], sb + ZARR * 4u + off);
                ldsm4(bl[np], sb + 2u * ZARR * 4u + off);
            }
            // fcol-style addressing: matrices interleave k-halves ->
            // n-group g uses regs {g, g+2}  (validated in R5 pass)
            #pragma unroll
            for (int mt = 0; mt < 2; mt++)
                #pragma unroll
                for (int nt = 0; nt < 8; nt++) {
                    const int np = nt >> 1, g = nt & 1;
                    uint32_t vh[2] = {bh[np][g], bh[np][g + 2]};
                    uint32_t vl[2] = {bl[np][g], bl[np][g + 2]};
                    mma_tf32(acc[mt][nt], ahi[mt], vh);
                    mma_tf32(acc[mt][nt], ahi[mt], vl);
                    mma_tf32(acc[mt][nt], alo[mt], vh);
                }
        }
        __syncthreads();
    }

    const int tr = lane >> 2, tc = (lane & 3) * 2;
    #pragma unroll
    for (int mt = 0; mt < 2; mt++)
        #pragma unroll
        for (int h = 0; h < 2; h++) {
            int row = row0 + warp_m * 32 + mt * 16 + h * 8 + tr;
            #pragma unroll
            for (int nt = 0; nt < 8; nt++) {
                int col = col0 + warp_n * 64 + nt * 8 + tc;
                float v0 = acc[mt][nt][h * 2 + 0] + bias[col];
                float v1 = acc[mt][nt][h * 2 + 1] + bias[col + 1];
                size_t o = (size_t)row * ldc + col;
                *reinterpret_cast<float2*>(C + o) = make_float2(v0, v1);
                if (write_bf) {
                    __nv_bfloat162 hp = __floats2bfloat162_rn(v0, v1);
                    *reinterpret_cast<uint32_t*>(Chi + o) = *reinterpret_cast<uint32_t*>(&hp);
                }
            }
        }
}

// ===========================================================================
// cov = zh @ cbh^T, single bf16 product (error ~0.05 abs, MARGIN covers it).
// CTA 128x128, BK=32, cp.async 2-stage. 8 warps 4x2, warp 32x64, m16n8k16.
#define CSTRIDE 40
#define CARR (128 * CSTRIDE)   // bf16 units

__device__ __forceinline__ void cov_loads(uint32_t sbase, int buf,
                                          int row0, int code0, int kc, int tid)
{
    #pragma unroll
    for (int t = 0; t < 2; t++) {
        int seg = tid + t * 256;
        int rr = seg >> 2, cc = (seg & 3) * 8;
        uint32_t so = sbase + (uint32_t)(buf * 2 * CARR + rr * CSTRIDE + cc) * 2u;
        CP16(so,             g_zh  + (size_t)(row0 + rr) * DEMB + kc + cc);
        CP16(so + CARR * 2u, g_cbh + (size_t)(code0 + rr) * DEMB + kc + cc);
    }
    CPCOMMIT();
}

__global__ __launch_bounds__(256, 2) void k_cov()
{
    __shared__ __align__(16) __nv_bfloat16 sm[2][2][CARR];   // 40 KB
    const int tid = threadIdx.x, lane = tid & 31, wid = tid >> 5;
    const int warp_m = wid & 3, warp_n = wid >> 2;
    const int row0 = blockIdx.y * 128, code0 = blockIdx.x * 128;
    const uint32_t sbase = smem_u32(&sm[0][0][0]);
    const int quad = lane >> 3;

    float acc[2][8][4];
    #pragma unroll
    for (int a = 0; a < 2; a++)
        #pragma unroll
        for (int b = 0; b < 8; b++)
            #pragma unroll
            for (int c = 0; c < 4; c++) acc[a][b][c] = 0.0f;

    cov_loads(sbase, 0, row0, code0, 0, tid);
    const int nch = DEMB >> 5;   // 8
    for (int c = 0; c < nch; c++) {
        if (c + 1 < nch) { cov_loads(sbase, (c + 1) & 1, row0, code0, (c + 1) * 32, tid); CPWAIT1(); }
        else CPWAIT0();
        __syncthreads();
        const uint32_t sb = sbase + (uint32_t)((c & 1) * 2 * CARR) * 2u;
        #pragma unroll
        for (int ks = 0; ks < 2; ks++) {
            const int k0 = ks * 16;
            uint32_t a[2][4], b[4][4];
            #pragma unroll
            for (int mt = 0; mt < 2; mt++)
                ldsm4(a[mt], sb + (uint32_t)(((warp_m * 32 + mt * 16 + (lane & 15)) * CSTRIDE)
                                             + k0 + (lane >> 4) * 8) * 2u);
            #pragma unroll
            for (int np = 0; np < 4; np++)
                ldsm4(b[np], sb + CARR * 2u +
                      (uint32_t)(((warp_n * 64 + np * 16 + (quad >> 1) * 8 + (lane & 7)) * CSTRIDE)
                                 + k0 + (quad & 1) * 8) * 2u);
            // quad-style addressing: matrix0=n0-7/k0-7, matrix1=n0-7/k8-15,
            // matrix2=n8-15/k0-7, matrix3=n8-15/k8-15 ->
            // n-group g uses CONSECUTIVE regs {2g, 2g+1}  (R6-validated; R7 bug was {g,g+2})
            #pragma unroll
            for (int mt = 0; mt < 2; mt++)
                #pragma unroll
                for (int nt = 0; nt < 8; nt++) {
                    const int np = nt >> 1, g = nt & 1;
                    uint32_t vb[2] = {b[np][g * 2], b[np][g * 2 + 1]};
                    mma_bf16(acc[mt][nt], a[mt], vb);
                }
        }
        __syncthreads();
    }

    const int tr = lane >> 2, tc = (lane & 3) * 2;
    #pragma unroll
    for (int mt = 0; mt < 2; mt++)
        #pragma unroll
        for (int h = 0; h < 2; h++) {
            int row = row0 + warp_m * 32 + mt * 16 + h * 8 + tr;
            #pragma unroll
            for (int nt = 0; nt < 8; nt++) {
                int col = code0 + warp_n * 64 + nt * 8 + tc;
                *reinterpret_cast<float2*>(g_cov + (size_t)row * KCB + col) =
                    make_float2(acc[mt][nt][h * 2], acc[mt][nt][h * 2 + 1]);
            }
        }
}

// ===========================================================================
// Refine + fused scatter: approx min from g_cov, exact fp32 distances for
// candidates, winner; then segment-sum z into g_upd, counts, loss.
__global__ __launch_bounds__(256) void k_refine(
    const float* __restrict__ cb, float* __restrict__ out)
{
    __shared__ float s_z[DEMB];
    __shared__ float s_red[256];
    __shared__ int   s_cand[64];
    __shared__ int   s_ncand;
    __shared__ unsigned long long s_best;

    const int row = blockIdx.x;
    const int t = threadIdx.x;
    const int wid = t >> 5, lane = t & 31;

    float zval = g_z[(size_t)row * DEMB + t];
    s_z[t] = zval;
    if (t == 0) { s_ncand = 0; s_best = 0xFFFFFFFFFFFFFFFFull; }

    float dt[4];
    float lm = 3.4e38f;
    #pragma unroll
    for (int i = 0; i < 4; i++) {
        int c = i * 256 + t;
        dt[i] = fmaf(-2.0f, g_cov[(size_t)row * KCB + c], g_sqr[c]);
        lm = fminf(lm, dt[i]);
    }
    s_red[t] = lm;
    __syncthreads();
    for (int s = 128; s > 0; s >>= 1) {
        if (t < s) s_red[t] = fminf(s_red[t], s_red[t + s]);
        __syncthreads();
    }
    const float thr = s_red[0] + MARGIN;
    __syncthreads();

    #pragma unroll
    for (int i = 0; i < 4; i++) {
        if (dt[i] <= thr) {
            int idx = atomicAdd(&s_ncand, 1);
            if (idx < 64) s_cand[idx] = i * 256 + t;
        }
    }
    __syncthreads();
    const int nc = s_ncand;

    if (nc <= 64) {
        for (int ci = wid; ci < nc; ci += 8) {
            int c = s_cand[ci];
            const float* cbr = cb + (size_t)c * DEMB;
            float dot = 0.0f;
            #pragma unroll
            for (int j = 0; j < 8; j++) dot = fmaf(s_z[lane + 32 * j], cbr[lane + 32 * j], dot);
            #pragma unroll
            for (int o = 16; o > 0; o >>= 1) dot += __shfl_xor_sync(0xffffffffu, dot, o);
            if (lane == 0) {
                float d = fmaf(-2.0f, dot, g_sqr[c]);
                unsigned u = __float_as_uint(d);
                u = (u & 0x80000000u) ? ~u : (u | 0x80000000u);
                atomicMin(&s_best, ((unsigned long long)u << 32) | (unsigned)c);
            }
        }
    } else {
        for (int c = wid; c < KCB; c += 8) {
            const float* cbr = cb + (size_t)c * DEMB;
            float dot = 0.0f;
            #pragma unroll
            for (int j = 0; j < 8; j++) dot = fmaf(s_z[lane + 32 * j], cbr[lane + 32 * j], dot);
            #pragma unroll
            for (int o = 16; o > 0; o >>= 1) dot += __shfl_xor_sync(0xffffffffu, dot, o);
            if (lane == 0) {
                float d = fmaf(-2.0f, dot, g_sqr[c]);
                unsigned u = __float_as_uint(d);
                u = (u & 0x80000000u) ? ~u : (u | 0x80000000u);
                atomicMin(&s_best, ((unsigned long long)u << 32) | (unsigned)c);
            }
        }
    }
    __syncthreads();

    // winner
    unsigned long long p = s_best;
    int code = (int)(unsigned)(p & 0xFFFFFFFFull);
    unsigned ue = (unsigned)(p >> 32);
    float dmin = (ue & 0x80000000u) ? __uint_as_float(ue & 0x7FFFFFFFu)
                                    : __uint_as_float(~ue);

    // fused scatter: segment-sum z, counts, loss
    atomicAdd(&g_upd[(size_t)code * DEMB + t], zval);
    float sq = zval * zval;
    #pragma unroll
    for (int o = 16; o > 0; o >>= 1) sq += __shfl_xor_sync(0xffffffffu, sq, o);
    if (lane == 0) s_red[wid] = sq;
    __syncthreads();
    if (t == 0) {
        float tot = 0.0f;
        #pragma unroll
        for (int w = 0; w < 8; w++) tot += s_red[w];
        g_codes[row] = code;
        g_dmin[row]  = dmin;
        out[OFF_CODES + row] = (float)code;
        atomicAdd(&g_loss, tot + dmin);
        atomicAdd(&g_cnt[code], 1.0f);
    }
}

// ===========================================================================
// transpose + tf32 hi/lo split
__global__ void k_trsplit(const float* __restrict__ src, float* __restrict__ hi,
                          float* __restrict__ lo, int R, int C) {
    int id = blockIdx.x * blockDim.x + threadIdx.x;
    int c = id / R, r = id - c * R;
    float v = src[(size_t)r * C + c];
    uint32_t h = f2tf32(v);
    float hf = __uint_as_float(h);
    hi[id] = hf;
    lo[id] = __uint_as_float(f2tf32(v - hf));
}

// codebook -> bf16 (hi only)
__global__ void k_convcb(const float* __restrict__ src, __nv_bfloat16* __restrict__ hi) {
    size_t i = ((size_t)blockIdx.x * blockDim.x + threadIdx.x) * 4;
    float4 v = *reinterpret_cast<const float4*>(src + i);
    __nv_bfloat162 h01 = __floats2bfloat162_rn(v.x, v.y);
    __nv_bfloat162 h23 = __floats2bfloat162_rn(v.z, v.w);
    uint2 hp;
    hp.x = *reinterpret_cast<uint32_t*>(&h01); hp.y = *reinterpret_cast<uint32_t*>(&h23);
    *reinterpret_cast<uint2*>(hi + i) = hp;
}

// ---------------------------------------------------------------------------
__global__ void k_init() {
    int i = blockIdx.x * blockDim.x + threadIdx.x;
    if (i < KCB * DEMB) g_upd[i] = 0.0f;
    if (i < KCB)        g_cnt[i] = 0.0f;
    if (i == 0)         g_loss  = 0.0f;
}

__global__ void k_sqr(const float* __restrict__ cb) {
    int k = blockIdx.x, j = threadIdx.x;
    float v = cb[k * DEMB + j];
    float s = v * v;
    #pragma unroll
    for (int o = 16; o > 0; o >>= 1) s += __shfl_xor_sync(0xffffffffu, s, o);
    __shared__ float wsum[8];
    if ((j & 31) == 0) wsum[j >> 5] = s;
    __syncthreads();
    if (j == 0) {
        float tot = 0.0f;
        #pragma unroll
        for (int w = 0; w < 8; w++) tot += wsum[w];
        g_sqr[k] = tot;
    }
}

__global__ __launch_bounds__(1024) void k_final_small(
    const float* __restrict__ ema_size_in, float* __restrict__ out)
{
    __shared__ float sh[1024];
    int t = threadIdx.x;
    float cnt = g_cnt[t];
    float esz = ema_size_in[t] + ALPHA * (cnt - ema_size_in[t]);
    out[OFF_EMA_SIZE + t] = esz;

    sh[t] = esz;
    __syncthreads();
    for (int s = 512; s > 0; s >>= 1) {
        if (t < s) sh[t] += sh[t + s];
        __syncthreads();
    }
    float n = sh[0];
    __syncthreads();

    float coef = n / (n + (float)KCB * EPSV);
    g_size[t]  = coef * (esz + EPSV);

    float p = cnt * (1.0f / (float)NROWS);
    float e = (cnt > 0.0f) ? (-p * logf(p)) : 0.0f;
    sh[t] = e;
    __syncthreads();
    for (int s = 512; s > 0; s >>= 1) {
        if (t < s) sh[t] += sh[t + s];
        __syncthreads();
    }
    if (t == 0) {
        out[OFF_ENT]    = sh[0] / logf(2.0f);
        out[OFF_EMB]    = g_loss;
        out[OFF_COMMIT] = g_loss;
    }
}

__global__ void k_ema(const float* __restrict__ ema_vecs_in, float* __restrict__ out) {
    int i = blockIdx.x * blockDim.x + threadIdx.x;
    float v = ema_vecs_in[i] + ALPHA * (g_upd[i] - ema_vecs_in[i]);
    out[OFF_EMA_VECS + i] = v;
    out[OFF_WEIGHT + i]   = v / g_size[i >> 8];
}

__global__ __launch_bounds__(256) void k_gather(float* __restrict__ out) {
    int row  = blockIdx.x;
    int code = g_codes[row];
    const float4* src = reinterpret_cast<const float4*>(g_Y + (size_t)code * DIN);
    float4* dst = reinterpret_cast<float4*>(out + OFF_X + (size_t)row * DIN);
    dst[threadIdx.x] = src[threadIdx.x];
}

// ---------------------------------------------------------------------------
extern "C" void kernel_launch(void* const* d_in, const int* in_sizes, int n_in,
                              void* d_out, int out_size) {
    const float* input    = (const float*)d_in[0];
    const float* W_send   = (const float*)d_in[1];
    const float* b_send   = (const float*)d_in[2];
    const float* W_recv   = (const float*)d_in[3];
    const float* b_recv   = (const float*)d_in[4];
    const float* codebook = (const float*)d_in[5];
    const float* ema_vecs = (const float*)d_in[6];
    const float* ema_size = (const float*)d_in[7];
    float* out = (float*)d_out;

    float *z_ptr, *Y_ptr, *wsh, *wsl, *wrh, *wrl;
    __nv_bfloat16 *zh, *cbh;
    cudaGetSymbolAddress((void**)&z_ptr, g_z);
    cudaGetSymbolAddress((void**)&Y_ptr, g_Y);
    cudaGetSymbolAddress((void**)&wsh, g_wsT_hi); cudaGetSymbolAddress((void**)&wsl, g_wsT_lo);
    cudaGetSymbolAddress((void**)&wrh, g_wrT_hi); cudaGetSymbolAddress((void**)&wrl, g_wrT_lo);
    cudaGetSymbolAddress((void**)&zh, g_zh);
    cudaGetSymbolAddress((void**)&cbh, g_cbh);

    cudaFuncSetAttribute(k_tgemm32, cudaFuncAttributeMaxDynamicSharedMemorySize, ZSMEM_BYTES);

    k_init<<<1024, 256>>>();                                              // 0
    k_trsplit<<<DIN * DEMB / 256, 256>>>(W_send, wsh, wsl, DIN, DEMB);    // 1
    // z = input @ W_send + b_send (3xTF32, fused bf16-hi z output)       // 2 (profiled slot)
    k_tgemm32<<<dim3(2, 128), 256, ZSMEM_BYTES>>>(input, wsh, wsl, b_send,
                                                  z_ptr, zh, DEMB, DIN, 1);
    k_sqr<<<KCB, 256>>>(codebook);                                        // 3
    k_convcb<<<KCB * DEMB / 1024, 256>>>(codebook, cbh);                  // 4
    k_trsplit<<<DIN * DEMB / 256, 256>>>(W_recv, wrh, wrl, DEMB, DIN);    // 5
    // Y = codebook @ W_recv + b_recv (3xTF32)                            // 6
    k_tgemm32<<<dim3(8, 8), 256, ZSMEM_BYTES>>>(codebook, wrh, wrl, b_recv,
                                                Y_ptr, (__nv_bfloat16*)nullptr,
                                                DIN, DEMB, 0);
    k_cov<<<dim3(8, 128), 256>>>();                                       // 7
    k_refine<<<NROWS, 256>>>(codebook, out);                              // 8 (fused scatter)
    k_final_small<<<1, 1024>>>(ema_size, out);                            // 9
    k_ema<<<1024, 256>>>(ema_vecs, out);                                  // 10
    k_gather<<<NROWS, 256>>>(out);                                        // 11
}